// round 5
// baseline (speedup 1.0000x reference)
#include <cuda_runtime.h>
#include <math.h>

// Problem constants
#define Bb 32
#define Tt 128
#define Hh 1024
#define Ll 2
#define Vv 32000
#define H3 3072          // 3*H
#define MROWS (Tt*Bb)    // 4096
#define BOS 1
#define NBLK 128         // persistent recurrence blocks (all resident on 148 SMs)

// ---------------- scratch (static device globals; no runtime allocation) ----
__device__ float g_gi[MROWS * H3];        // gi for the current layer [t*B+b][3H]
__device__ float g_h0[MROWS * Hh];        // layer-0 outputs [t*B+b][H]
__device__ float g_hs[MROWS * Hh];        // layer-1 outputs [b*T+t][H]
__device__ float g_hbuf[2][Bb * Hh];      // ping-pong hidden state
__device__ int   g_ids[MROWS];            // teacher-forced input ids, [t*B+b]
__device__ float g_lse[MROWS];            // per-row logsumexp
__device__ unsigned g_bar;                // grid-barrier counter

// ---------------- tiny helpers ----------------------------------------------
__global__ void copy_kernel(const float* __restrict__ src, float* __restrict__ dst, int n) {
    int i = blockIdx.x * blockDim.x + threadIdx.x;
    if (i < n) dst[i] = src[i];
}
__global__ void zero_bar_kernel() { g_bar = 0u; }

// ---------------- ids: [BOS, target[:, :-1]] --------------------------------
__global__ void ids_kernel(const int* __restrict__ target) {
    int i = blockIdx.x * blockDim.x + threadIdx.x;   // i = t*B + b
    if (i >= MROWS) return;
    int t = i / Bb, b = i % Bb;
    g_ids[i] = (t == 0) ? BOS : target[b * Tt + (t - 1)];
}

// ---------------- persistent GRU layer: all T steps in one launch ------------
// Grid: NBLK=128 blocks x 256 threads, 1 block/SM -> all resident, barrier safe.
// Block owns 8 h-columns (24 whh rows). Warp w handles batch rows 4w..4w+3;
// lane owns a 32-wide K chunk. SMEM cross-lane reduction, local gate math,
// ping-pong h buffer, atomic-counter grid barrier with nanosleep backoff.
__global__ void __launch_bounds__(256, 1) gru_layer_kernel(
    const float* __restrict__ gi,     // [T][B][3H]
    const float* __restrict__ whh,    // [3H][H]
    const float* __restrict__ bhh,    // [3H]
    float* __restrict__ hist,         // output history
    int tStride, int bStride)
{
    __shared__ float part[256][33];   // per-lane partials (pad: conflict-free)
    __shared__ float ghS[24][32];     // reduced gh for owned rows x batch
    const int tid  = threadIdx.x;
    const int lane = tid & 31;
    const int w    = tid >> 5;
    const int j0   = blockIdx.x * 8;  // owned h-columns
    const int bbase = w * 4;

    // gate-math thread mapping (fixed across steps)
    const int gb = tid >> 3;          // batch row 0..31
    const int gj = tid & 7;           // owned column idx 0..7
    const int j  = j0 + gj;
    const float bhr = bhh[j];
    const float bhz = bhh[Hh + j];
    const float bhn = bhh[2 * Hh + j];

    for (int t = 0; t < Tt; t++) {
        const float* __restrict__ hcur = g_hbuf[t & 1];
        float* __restrict__ hnxt = g_hbuf[(t + 1) & 1];

        #pragma unroll
        for (int g = 0; g < 3; g++) {
            float acc[8][4];
            #pragma unroll
            for (int r = 0; r < 8; r++)
                #pragma unroll
                for (int b = 0; b < 4; b++) acc[r][b] = 0.f;

            const float* wbase = whh + ((size_t)(g * Hh + j0)) * Hh + lane * 32;
            const float* hbase = hcur + (size_t)bbase * Hh + lane * 32;

            #pragma unroll
            for (int kk = 0; kk < 32; kk += 4) {
                float4 hv[4];
                #pragma unroll
                for (int b = 0; b < 4; b++)
                    hv[b] = *(const float4*)(hbase + (size_t)b * Hh + kk);
                #pragma unroll
                for (int r = 0; r < 8; r++) {
                    float4 wv = *(const float4*)(wbase + (size_t)r * Hh + kk);
                    #pragma unroll
                    for (int b = 0; b < 4; b++) {
                        acc[r][b] += wv.x * hv[b].x;
                        acc[r][b] += wv.y * hv[b].y;
                        acc[r][b] += wv.z * hv[b].z;
                        acc[r][b] += wv.w * hv[b].w;
                    }
                }
            }
            // dump partials: index (w*32 + r*4 + b) x lane
            #pragma unroll
            for (int r = 0; r < 8; r++)
                #pragma unroll
                for (int b = 0; b < 4; b++)
                    part[(w << 5) + (r << 2) + b][lane] = acc[r][b];
            __syncthreads();
            // cross-lane reduce: one output per thread
            {
                float s = 0.f;
                #pragma unroll
                for (int l = 0; l < 32; l++) s += part[tid][l];
                int rr = (tid >> 2) & 7, bb = tid & 3, ww = tid >> 5;
                ghS[g * 8 + rr][ww * 4 + bb] = s;
            }
            __syncthreads();
        }

        // gate math for owned (b, j)
        {
            const float* git = gi + ((size_t)t * Bb + gb) * H3;
            float ghr = ghS[gj][gb] + bhr;
            float ghz = ghS[8 + gj][gb] + bhz;
            float ghn = ghS[16 + gj][gb] + bhn;
            float r_ = 1.f / (1.f + expf(-(git[j] + ghr)));
            float z_ = 1.f / (1.f + expf(-(git[Hh + j] + ghz)));
            float n_ = tanhf(git[2 * Hh + j] + r_ * ghn);
            float hp = hcur[(size_t)gb * Hh + j];
            float hn = (1.f - z_) * n_ + z_ * hp;
            hist[(size_t)t * tStride + (size_t)gb * bStride + j] = hn;
            hnxt[(size_t)gb * Hh + j] = hn;
        }

        // grid barrier: all writes visible, then proceed in lockstep
        __threadfence();
        __syncthreads();
        if (tid == 0) {
            atomicAdd(&g_bar, 1u);
            unsigned tgt = (unsigned)(NBLK * (t + 1));
            volatile unsigned* vb = &g_bar;
            while (*vb < tgt) { __nanosleep(64); }
        }
        __syncthreads();
        __threadfence();
    }
}

// ---------------- 128x128 fp32 SGEMM:  C[m][n] = sum_k A[m][k]*W[n][k] + bias[n]
template<int GATHER>
__global__ void __launch_bounds__(256, 2) sgemm_kernel(
    const float* __restrict__ A, const float* __restrict__ Wt,
    const float* __restrict__ bias, float* __restrict__ C,
    int N, int Kdim, const float* __restrict__ emb)
{
    __shared__ float As[8][128];
    __shared__ float Bs[8][128];
    int tid = threadIdx.x;
    int m0 = blockIdx.y * 128;
    int n0 = blockIdx.x * 128;
    int tx = tid & 15, ty = tid >> 4;
    float acc[8][8];
    #pragma unroll
    for (int i = 0; i < 8; i++)
        #pragma unroll
        for (int j = 0; j < 8; j++) acc[i][j] = 0.f;

    int lr = tid >> 1;
    int lk = (tid & 1) * 4;
    const float* arow;
    if (GATHER) arow = emb + (size_t)g_ids[m0 + lr] * Kdim;
    else        arow = A + (size_t)(m0 + lr) * Kdim;
    const float* brow = Wt + (size_t)(n0 + lr) * Kdim;

    for (int k0 = 0; k0 < Kdim; k0 += 8) {
        float4 av = *(const float4*)(arow + k0 + lk);
        float4 bv = *(const float4*)(brow + k0 + lk);
        As[lk + 0][lr] = av.x; As[lk + 1][lr] = av.y;
        As[lk + 2][lr] = av.z; As[lk + 3][lr] = av.w;
        Bs[lk + 0][lr] = bv.x; Bs[lk + 1][lr] = bv.y;
        Bs[lk + 2][lr] = bv.z; Bs[lk + 3][lr] = bv.w;
        __syncthreads();
        #pragma unroll
        for (int kk = 0; kk < 8; kk++) {
            float a[8], b[8];
            #pragma unroll
            for (int i = 0; i < 8; i++) a[i] = As[kk][ty + 16 * i];
            #pragma unroll
            for (int j = 0; j < 8; j++) b[j] = Bs[kk][tx + 16 * j];
            #pragma unroll
            for (int i = 0; i < 8; i++)
                #pragma unroll
                for (int j = 0; j < 8; j++)
                    acc[i][j] += a[i] * b[j];
        }
        __syncthreads();
    }
    #pragma unroll
    for (int i = 0; i < 8; i++) {
        int m = m0 + ty + 16 * i;
        #pragma unroll
        for (int j = 0; j < 8; j++) {
            int n = n0 + tx + 16 * j;
            C[(size_t)m * N + n] = acc[i][j] + (bias ? bias[n] : 0.f);
        }
    }
}

// ---------------- per-row logsumexp over V ----------------------------------
__global__ void lse_kernel(const float* __restrict__ logits) {
    int row = blockIdx.x;
    const float* p = logits + (size_t)row * Vv;
    __shared__ float warpred[8];
    int lane = threadIdx.x & 31, wid = threadIdx.x >> 5;

    float mx = -1e30f;
    for (int i = threadIdx.x; i < Vv; i += 256) mx = fmaxf(mx, p[i]);
    #pragma unroll
    for (int s = 16; s > 0; s >>= 1)
        mx = fmaxf(mx, __shfl_xor_sync(0xffffffffu, mx, s));
    if (lane == 0) warpred[wid] = mx;
    __syncthreads();
    mx = warpred[lane & 7];
    #pragma unroll
    for (int s = 4; s > 0; s >>= 1)
        mx = fmaxf(mx, __shfl_xor_sync(0xffffffffu, mx, s));
    mx = __shfl_sync(0xffffffffu, mx, 0);

    float sum = 0.f;
    for (int i = threadIdx.x; i < Vv; i += 256) sum += expf(p[i] - mx);
    #pragma unroll
    for (int s = 16; s > 0; s >>= 1)
        sum += __shfl_xor_sync(0xffffffffu, sum, s);
    __syncthreads();
    if (lane == 0) warpred[wid] = sum;
    __syncthreads();
    if (threadIdx.x == 0) {
        float tot = 0.f;
        #pragma unroll
        for (int w = 0; w < 8; w++) tot += warpred[w];
        g_lse[row] = mx + logf(tot);
    }
}

__global__ void sub_kernel(float* __restrict__ out) {
    int row = blockIdx.y;
    int c = blockIdx.x * 256 + threadIdx.x;
    out[(size_t)row * Vv + c] -= g_lse[row];
}

// ---------------- host driver ------------------------------------------------
extern "C" void kernel_launch(void* const* d_in, const int* in_sizes, int n_in,
                              void* d_out, int out_size) {
    const float* enc_h  = (const float*)d_in[1];
    const int*   target = (const int*)  d_in[2];
    const float* emb    = (const float*)d_in[3];
    const float* w_ih   = (const float*)d_in[4];
    const float* w_hh   = (const float*)d_in[5];
    const float* b_ih   = (const float*)d_in[6];
    const float* b_hh   = (const float*)d_in[7];
    const float* w_out  = (const float*)d_in[8];
    const float* b_out  = (const float*)d_in[9];
    float* out = (float*)d_out;

    float *p_gi, *p_h0, *p_hs, *p_hbuf;
    cudaGetSymbolAddress((void**)&p_gi,   g_gi);
    cudaGetSymbolAddress((void**)&p_h0,   g_h0);
    cudaGetSymbolAddress((void**)&p_hs,   g_hs);
    cudaGetSymbolAddress((void**)&p_hbuf, g_hbuf);

    float* hfinal = out + (size_t)MROWS * Vv;   // [L][B][H] tail of output

    // teacher-forced ids
    ids_kernel<<<(MROWS + 255) / 256, 256, 0, 0>>>(target);

    // ---- layer 0: gi0 = embed(ids) @ w_ih0^T + b_ih0 -----------------------
    sgemm_kernel<1><<<dim3(H3 / 128, MROWS / 128), 256, 0, 0>>>(
        nullptr, w_ih, b_ih, p_gi, H3, Hh, emb);

    // layer-0 recurrence (persistent)
    copy_kernel<<<(Bb * Hh + 255) / 256, 256, 0, 0>>>(enc_h, p_hbuf, Bb * Hh);
    zero_bar_kernel<<<1, 1, 0, 0>>>();
    gru_layer_kernel<<<NBLK, 256, 0, 0>>>(
        p_gi, w_hh, b_hh, p_h0, Bb * Hh, Hh);
    // final h of layer 0 lives in hbuf[T&1] = hbuf[0]
    copy_kernel<<<(Bb * Hh + 255) / 256, 256, 0, 0>>>(p_hbuf, hfinal, Bb * Hh);

    // ---- layer 1: gi1 = h0 @ w_ih1^T + b_ih1 -------------------------------
    sgemm_kernel<0><<<dim3(H3 / 128, MROWS / 128), 256, 0, 0>>>(
        p_h0, w_ih + (size_t)H3 * Hh, b_ih + H3, p_gi, H3, Hh, nullptr);

    // layer-1 recurrence (persistent); history in [b][t][h] order
    copy_kernel<<<(Bb * Hh + 255) / 256, 256, 0, 0>>>(
        enc_h + Bb * Hh, p_hbuf, Bb * Hh);
    zero_bar_kernel<<<1, 1, 0, 0>>>();
    gru_layer_kernel<<<NBLK, 256, 0, 0>>>(
        p_gi, w_hh + (size_t)H3 * Hh, b_hh + H3, p_hs, Hh, Tt * Hh);
    copy_kernel<<<(Bb * Hh + 255) / 256, 256, 0, 0>>>(
        p_hbuf, hfinal + Bb * Hh, Bb * Hh);

    // ---- logits = hs @ w_out^T + b_out  -> d_out[b][t][v] ------------------
    sgemm_kernel<0><<<dim3(Vv / 128, MROWS / 128), 256, 0, 0>>>(
        p_hs, w_out, b_out, out, Vv, Hh, nullptr);

    // ---- log_softmax -------------------------------------------------------
    lse_kernel<<<MROWS, 256, 0, 0>>>(out);
    sub_kernel<<<dim3(Vv / 256, MROWS), 256, 0, 0>>>(out);
}

// round 9
// speedup vs baseline: 3.4110x; 3.4110x over previous
#include <cuda_runtime.h>
#include <cuda_bf16.h>
#include <math.h>
#include <stdint.h>

// Problem constants
#define Bb 32
#define Tt 128
#define Hh 1024
#define Ll 2
#define Vv 32000
#define H3 3072          // 3*H
#define MROWS (Tt*Bb)    // 4096
#define BOS 1
#define NBLK 128         // persistent recurrence blocks (all resident)

// Logits HMMA tiling
#define MT 128           // block M tile
#define NT 128           // block N tile
#define KC 64            // K chunk (bf16) = 128 bytes/row
#define NKC (Hh / KC)    // 16 chunks
#define ATILEB (MT * 128)   // 16 KB
#define BTILEB (NT * 128)   // 16 KB
#define LSMEM (2 * (ATILEB + BTILEB))   // 64 KB

// ---------------- scratch (static device globals) ---------------------------
__device__ float g_gi[MROWS * H3];            // gi for current layer
__device__ float g_h0[MROWS * Hh];            // layer-0 outputs [t*B+b][H]
__device__ __nv_bfloat16 g_hsb[MROWS * Hh];   // layer-1 outputs bf16 [b*T+t][H]
__device__ __nv_bfloat16 g_wob[(size_t)Vv * Hh]; // w_out bf16
__device__ float g_hbuf[2][Bb * Hh];          // ping-pong hidden state
__device__ int   g_ids[MROWS];
__device__ float g_lse[MROWS];
__device__ unsigned g_bar;

// ---------------- PTX helpers (all arch-portable: sm_80+) --------------------
__device__ __forceinline__ uint32_t smem_u32(const void* p) {
    uint32_t a;
    asm("{ .reg .u64 t; cvta.to.shared.u64 t, %1; cvt.u32.u64 %0, t; }"
        : "=r"(a) : "l"(p));
    return a;
}
__device__ __forceinline__ void cp_async16(uint32_t s, const void* g) {
    asm volatile("cp.async.cg.shared.global [%0], [%1], 16;"
                 :: "r"(s), "l"(g) : "memory");
}
#define CP_COMMIT() asm volatile("cp.async.commit_group;" ::: "memory")
#define CP_WAIT1()  asm volatile("cp.async.wait_group 1;" ::: "memory")
#define CP_WAIT0()  asm volatile("cp.async.wait_group 0;" ::: "memory")
#define LDSM4(r, addr) \
    asm volatile("ldmatrix.sync.aligned.m8n8.x4.shared.b16 {%0,%1,%2,%3}, [%4];" \
        : "=r"((r)[0]), "=r"((r)[1]), "=r"((r)[2]), "=r"((r)[3]) : "r"(addr))
#define MMA16816(c, a, b0, b1) \
    asm volatile("mma.sync.aligned.m16n8k16.row.col.f32.bf16.bf16.f32 " \
        "{%0,%1,%2,%3}, {%4,%5,%6,%7}, {%8,%9}, {%0,%1,%2,%3};" \
        : "+f"((c)[0]), "+f"((c)[1]), "+f"((c)[2]), "+f"((c)[3]) \
        : "r"((a)[0]), "r"((a)[1]), "r"((a)[2]), "r"((a)[3]), "r"(b0), "r"(b1))

// ---------------- tiny helpers ----------------------------------------------
__global__ void copy_kernel(const float* __restrict__ src, float* __restrict__ dst, int n) {
    int i = blockIdx.x * blockDim.x + threadIdx.x;
    if (i < n) dst[i] = src[i];
}
__global__ void zero_bar_kernel() { g_bar = 0u; }
__global__ void wconv_kernel(const float* __restrict__ w) {
    size_t n = (size_t)Vv * Hh;
    size_t stride = (size_t)gridDim.x * blockDim.x;
    for (size_t i = blockIdx.x * (size_t)blockDim.x + threadIdx.x; i < n; i += stride)
        g_wob[i] = __float2bfloat16(w[i]);
}
__global__ void ids_kernel(const int* __restrict__ target) {
    int i = blockIdx.x * blockDim.x + threadIdx.x;
    if (i >= MROWS) return;
    int t = i / Bb, b = i % Bb;
    g_ids[i] = (t == 0) ? BOS : target[b * Tt + (t - 1)];
}

// ---------------- persistent GRU layer (coalesced) ---------------------------
// 128 blocks x 256 thr, 1/SM -> all resident. Block owns 8 h-cols (24 whh rows).
// Warp = (rg 0..3, bg 0..1): 6 rows x 16 batches, lane owns k = k0 + lane*4
// (coalesced: every LDG.128 touches the minimal 4 lines). Tree shfl reduction.
__device__ __forceinline__ void reduce_group(float* v, int lane) {
    #pragma unroll
    for (int s = 16; s >= 1; s >>= 1) {
        #pragma unroll
        for (int i = 0; i < s; i++) {
            float keep = (lane & s) ? v[i + s] : v[i];
            float send = (lane & s) ? v[i] : v[i + s];
            float recv = __shfl_xor_sync(0xffffffffu, send, s);
            v[i] = keep + recv;
        }
    }
}

__global__ void __launch_bounds__(256) gru_layer_kernel(
    const float* __restrict__ gi,     // [T][B][3H]
    const float* __restrict__ whh,    // [3H][H]
    const float* __restrict__ bhh,    // [3H]
    float* __restrict__ hist,         // fp32 history (or null)
    __nv_bfloat16* __restrict__ histb,// bf16 history (or null)
    int tS, int bS)
{
    __shared__ float ghS[24][33];
    const int tid  = threadIdx.x;
    const int lane = tid & 31;
    const int w    = tid >> 5;
    const int rg   = w >> 1;          // 0..3: row group (6 rows)
    const int bg   = w & 1;           // 0..1: batch group (16)
    const int j0   = blockIdx.x * 8;

    const int gb = tid >> 3;          // gate-math batch 0..31
    const int gj = tid & 7;           // gate-math col 0..7
    const int j  = j0 + gj;
    const float bhr = bhh[j];
    const float bhz = bhh[Hh + j];
    const float bhn = bhh[2 * Hh + j];

    for (int t = 0; t < Tt; t++) {
        const float* __restrict__ hcur = g_hbuf[t & 1];
        float* __restrict__ hnxt = g_hbuf[(t + 1) & 1];

        float acc[96];
        #pragma unroll
        for (int i = 0; i < 96; i++) acc[i] = 0.f;

        for (int i8 = 0; i8 < 8; i8++) {
            const int k0 = i8 * 128 + lane * 4;
            float4 hv[16];
            #pragma unroll
            for (int b = 0; b < 16; b++)
                hv[b] = *(const float4*)(hcur + (size_t)(bg * 16 + b) * Hh + k0);
            #pragma unroll
            for (int q = 0; q < 6; q++) {
                int rid = rg * 6 + q;
                int wrow = (rid >> 3) * Hh + j0 + (rid & 7);   // g*H + (j0+c)
                float4 wv = *(const float4*)(whh + (size_t)wrow * Hh + k0);
                #pragma unroll
                for (int b = 0; b < 16; b++) {
                    acc[q * 16 + b] += wv.x * hv[b].x;
                    acc[q * 16 + b] += wv.y * hv[b].y;
                    acc[q * 16 + b] += wv.z * hv[b].z;
                    acc[q * 16 + b] += wv.w * hv[b].w;
                }
            }
        }
        // cross-lane reduce: lane l ends owning flat index l of each 32-group
        reduce_group(acc, lane);
        reduce_group(acc + 32, lane);
        reduce_group(acc + 64, lane);
        #pragma unroll
        for (int g3 = 0; g3 < 3; g3++) {
            int flat = g3 * 32 + lane;
            int q = flat >> 4, bcol = flat & 15;
            int rid = rg * 6 + q;
            ghS[rid][bg * 16 + bcol] = acc[g3 * 32];
        }
        __syncthreads();

        // gate math for owned (gb, j)
        {
            const float* git = gi + ((size_t)t * Bb + gb) * H3;
            float ghr = ghS[gj][gb] + bhr;
            float ghz = ghS[8 + gj][gb] + bhz;
            float ghn = ghS[16 + gj][gb] + bhn;
            float r_ = 1.f / (1.f + expf(-(git[j] + ghr)));
            float z_ = 1.f / (1.f + expf(-(git[Hh + j] + ghz)));
            float n_ = tanhf(git[2 * Hh + j] + r_ * ghn);
            float hp = hcur[(size_t)gb * Hh + j];
            float hn = (1.f - z_) * n_ + z_ * hp;
            size_t oidx = (size_t)t * tS + (size_t)gb * bS + j;
            if (histb) histb[oidx] = __float2bfloat16(hn);
            else       hist[oidx] = hn;
            hnxt[(size_t)gb * Hh + j] = hn;
        }

        // grid barrier
        __threadfence();
        __syncthreads();
        if (tid == 0) {
            atomicAdd(&g_bar, 1u);
            unsigned tgt = (unsigned)(NBLK * (t + 1));
            volatile unsigned* vb = &g_bar;
            while (*vb < tgt) { __nanosleep(32); }
        }
        __syncthreads();
        __threadfence();
    }
}

// ---------------- fp32 SGEMM for gi (known-good) -----------------------------
template<int GATHER>
__global__ void __launch_bounds__(256, 2) sgemm_kernel(
    const float* __restrict__ A, const float* __restrict__ Wt,
    const float* __restrict__ bias, float* __restrict__ C,
    int N, int Kdim, const float* __restrict__ emb)
{
    __shared__ float As[8][128];
    __shared__ float Bs[8][128];
    int tid = threadIdx.x;
    int m0 = blockIdx.y * 128;
    int n0 = blockIdx.x * 128;
    int tx = tid & 15, ty = tid >> 4;
    float acc[8][8];
    #pragma unroll
    for (int i = 0; i < 8; i++)
        #pragma unroll
        for (int jj = 0; jj < 8; jj++) acc[i][jj] = 0.f;

    int lr = tid >> 1;
    int lk = (tid & 1) * 4;
    const float* arow;
    if (GATHER) arow = emb + (size_t)g_ids[m0 + lr] * Kdim;
    else        arow = A + (size_t)(m0 + lr) * Kdim;
    const float* brow = Wt + (size_t)(n0 + lr) * Kdim;

    for (int k0 = 0; k0 < Kdim; k0 += 8) {
        float4 av = *(const float4*)(arow + k0 + lk);
        float4 bv = *(const float4*)(brow + k0 + lk);
        As[lk + 0][lr] = av.x; As[lk + 1][lr] = av.y;
        As[lk + 2][lr] = av.z; As[lk + 3][lr] = av.w;
        Bs[lk + 0][lr] = bv.x; Bs[lk + 1][lr] = bv.y;
        Bs[lk + 2][lr] = bv.z; Bs[lk + 3][lr] = bv.w;
        __syncthreads();
        #pragma unroll
        for (int kk = 0; kk < 8; kk++) {
            float a[8], b[8];
            #pragma unroll
            for (int i = 0; i < 8; i++) a[i] = As[kk][ty + 16 * i];
            #pragma unroll
            for (int jj = 0; jj < 8; jj++) b[jj] = Bs[kk][tx + 16 * jj];
            #pragma unroll
            for (int i = 0; i < 8; i++)
                #pragma unroll
                for (int jj = 0; jj < 8; jj++)
                    acc[i][jj] += a[i] * b[jj];
        }
        __syncthreads();
    }
    #pragma unroll
    for (int i = 0; i < 8; i++) {
        int m = m0 + ty + 16 * i;
        #pragma unroll
        for (int jj = 0; jj < 8; jj++) {
            int n = n0 + tx + 16 * jj;
            C[(size_t)m * N + n] = acc[i][jj] + (bias ? bias[n] : 0.f);
        }
    }
}

// ---------------- bf16 HMMA logits GEMM (mma.sync, arch-portable) ------------
// D[m][n] = sum_k hsb[m][k]*wob[n][k] + bias[n].
// Block 128x128, 8 warps (64Mx32N each), KC=64 chunks, 2-stage cp.async,
// 128B swizzled smem rows (chunk ^ (row&7)) -> conflict-free LDSM/STS.
// B stored [n][k] row-major == col-major kxn, so NON-trans ldmatrix gives the
// B fragment directly (lane -> n=lane/4, k=2*(lane%4)).
#define PREF(ch, p) do {                                                        \
    int _k0 = (ch) * KC;                                                        \
    uint32_t _ab = sb + (p) * ATILEB;                                           \
    uint32_t _bb = sb + 2 * ATILEB + (p) * BTILEB;                              \
    _Pragma("unroll")                                                           \
    for (int _it = 0; _it < 4; _it++) {                                         \
        int _idx = _it * 256 + tid, _row = _idx >> 3, _c = _idx & 7;            \
        cp_async16(_ab + _row * 128 + ((_c ^ (_row & 7)) * 16),                 \
                   hsb + (size_t)(m0 + _row) * Hh + _k0 + _c * 8);              \
        cp_async16(_bb + _row * 128 + ((_c ^ (_row & 7)) * 16),                 \
                   wob + (size_t)(n0 + _row) * Hh + _k0 + _c * 8);              \
    }                                                                           \
    CP_COMMIT();                                                                \
} while (0)

__global__ void __launch_bounds__(256) logits_mma_kernel(
    const __nv_bfloat16* __restrict__ hsb,
    const __nv_bfloat16* __restrict__ wob,
    const float* __restrict__ bias,
    float* __restrict__ out)
{
    extern __shared__ char smem[];
    const int tid  = threadIdx.x;
    const int lane = tid & 31;
    const int warp = tid >> 5;
    const int m0 = blockIdx.y * MT;
    const int n0 = blockIdx.x * NT;
    const int wm = (warp & 1) * 64;
    const int wn = (warp >> 1) * 32;
    uint32_t sb = smem_u32(smem);

    float acc[4][4][4];
    #pragma unroll
    for (int i = 0; i < 4; i++)
        #pragma unroll
        for (int jj = 0; jj < 4; jj++)
            #pragma unroll
            for (int k = 0; k < 4; k++) acc[i][jj][k] = 0.f;

    PREF(0, 0);
    for (int ch = 0; ch < NKC; ch++) {
        const int p = ch & 1;
        if (ch + 1 < NKC) { PREF(ch + 1, (ch + 1) & 1); CP_WAIT1(); }
        else              { CP_WAIT0(); }
        __syncthreads();

        const uint32_t ab = sb + p * ATILEB;
        const uint32_t bb = sb + 2 * ATILEB + p * BTILEB;
        #pragma unroll
        for (int k16 = 0; k16 < 4; k16++) {
            uint32_t a[4][4], b[2][4];
            #pragma unroll
            for (int mf = 0; mf < 4; mf++) {
                int row = wm + mf * 16 + (lane & 7) + ((lane >> 3) & 1) * 8;
                int c = k16 * 2 + (lane >> 4);
                LDSM4(a[mf], ab + row * 128 + ((c ^ (row & 7)) * 16));
            }
            #pragma unroll
            for (int nf2 = 0; nf2 < 2; nf2++) {
                // m0=(n0-7,klo) m1=(n0-7,khi) m2=(n8-15,klo) m3=(n8-15,khi)
                int row = wn + nf2 * 16 + (lane & 7) + ((lane >> 4) & 1) * 8;
                int c = k16 * 2 + ((lane >> 3) & 1);
                LDSM4(b[nf2], bb + row * 128 + ((c ^ (row & 7)) * 16));
            }
            #pragma unroll
            for (int mf = 0; mf < 4; mf++)
                #pragma unroll
                for (int nf = 0; nf < 4; nf++)
                    MMA16816(acc[mf][nf], a[mf],
                             b[nf >> 1][(nf & 1) * 2], b[nf >> 1][(nf & 1) * 2 + 1]);
        }
        __syncthreads();
    }

    // epilogue: direct stores with bias
    #pragma unroll
    for (int mf = 0; mf < 4; mf++) {
        #pragma unroll
        for (int nf = 0; nf < 4; nf++) {
            int r  = m0 + wm + mf * 16 + (lane >> 2);
            int cg = n0 + wn + nf * 8 + (lane & 3) * 2;
            float b0 = bias[cg], b1 = bias[cg + 1];
            float2 v0 = make_float2(acc[mf][nf][0] + b0, acc[mf][nf][1] + b1);
            float2 v1 = make_float2(acc[mf][nf][2] + b0, acc[mf][nf][3] + b1);
            *(float2*)(out + (size_t)r * Vv + cg) = v0;
            *(float2*)(out + (size_t)(r + 8) * Vv + cg) = v1;
        }
    }
}

// ---------------- log_softmax ------------------------------------------------
__global__ void lse_kernel(const float* __restrict__ logits) {
    int row = blockIdx.x;
    const float* p = logits + (size_t)row * Vv;
    __shared__ float warpred[8];
    int lane = threadIdx.x & 31, wid = threadIdx.x >> 5;

    float mx = -1e30f;
    for (int i = threadIdx.x; i < Vv; i += 256) mx = fmaxf(mx, p[i]);
    #pragma unroll
    for (int s = 16; s > 0; s >>= 1)
        mx = fmaxf(mx, __shfl_xor_sync(0xffffffffu, mx, s));
    if (lane == 0) warpred[wid] = mx;
    __syncthreads();
    mx = warpred[lane & 7];
    #pragma unroll
    for (int s = 4; s > 0; s >>= 1)
        mx = fmaxf(mx, __shfl_xor_sync(0xffffffffu, mx, s));
    mx = __shfl_sync(0xffffffffu, mx, 0);

    float sum = 0.f;
    for (int i = threadIdx.x; i < Vv; i += 256) sum += expf(p[i] - mx);
    #pragma unroll
    for (int s = 16; s > 0; s >>= 1)
        sum += __shfl_xor_sync(0xffffffffu, sum, s);
    __syncthreads();
    if (lane == 0) warpred[wid] = sum;
    __syncthreads();
    if (threadIdx.x == 0) {
        float tot = 0.f;
        #pragma unroll
        for (int w = 0; w < 8; w++) tot += warpred[w];
        g_lse[row] = mx + logf(tot);
    }
}

__global__ void sub_kernel(float* __restrict__ out) {
    int row = blockIdx.y;
    int c = blockIdx.x * 256 + threadIdx.x;
    out[(size_t)row * Vv + c] -= g_lse[row];
}

// ---------------- host driver ------------------------------------------------
extern "C" void kernel_launch(void* const* d_in, const int* in_sizes, int n_in,
                              void* d_out, int out_size) {
    const float* enc_h  = (const float*)d_in[1];
    const int*   target = (const int*)  d_in[2];
    const float* emb    = (const float*)d_in[3];
    const float* w_ih   = (const float*)d_in[4];
    const float* w_hh   = (const float*)d_in[5];
    const float* b_ih   = (const float*)d_in[6];
    const float* b_hh   = (const float*)d_in[7];
    const float* w_out  = (const float*)d_in[8];
    const float* b_out  = (const float*)d_in[9];
    float* out = (float*)d_out;

    float *p_gi, *p_h0, *p_hbuf;
    __nv_bfloat16 *p_hsb, *p_wob;
    cudaGetSymbolAddress((void**)&p_gi,   g_gi);
    cudaGetSymbolAddress((void**)&p_h0,   g_h0);
    cudaGetSymbolAddress((void**)&p_hsb,  g_hsb);
    cudaGetSymbolAddress((void**)&p_wob,  g_wob);
    cudaGetSymbolAddress((void**)&p_hbuf, g_hbuf);

    float* hfinal = out + (size_t)MROWS * Vv;

    cudaFuncSetAttribute(logits_mma_kernel,
                         cudaFuncAttributeMaxDynamicSharedMemorySize, LSMEM);

    // prep: ids + w_out bf16 conversion
    ids_kernel<<<(MROWS + 255) / 256, 256, 0, 0>>>(target);
    wconv_kernel<<<4096, 256, 0, 0>>>(w_out);

    // ---- layer 0 -----------------------------------------------------------
    sgemm_kernel<1><<<dim3(H3 / 128, MROWS / 128), 256, 0, 0>>>(
        nullptr, w_ih, b_ih, p_gi, H3, Hh, emb);
    copy_kernel<<<(Bb * Hh + 255) / 256, 256, 0, 0>>>(enc_h, p_hbuf, Bb * Hh);
    zero_bar_kernel<<<1, 1, 0, 0>>>();
    gru_layer_kernel<<<NBLK, 256, 0, 0>>>(
        p_gi, w_hh, b_hh, p_h0, nullptr, Bb * Hh, Hh);
    copy_kernel<<<(Bb * Hh + 255) / 256, 256, 0, 0>>>(p_hbuf, hfinal, Bb * Hh);

    // ---- layer 1 -----------------------------------------------------------
    sgemm_kernel<0><<<dim3(H3 / 128, MROWS / 128), 256, 0, 0>>>(
        p_h0, w_ih + (size_t)H3 * Hh, b_ih + H3, p_gi, H3, Hh, nullptr);
    copy_kernel<<<(Bb * Hh + 255) / 256, 256, 0, 0>>>(
        enc_h + Bb * Hh, p_hbuf, Bb * Hh);
    zero_bar_kernel<<<1, 1, 0, 0>>>();
    gru_layer_kernel<<<NBLK, 256, 0, 0>>>(
        p_gi, w_hh + (size_t)H3 * Hh, b_hh + H3, nullptr, p_hsb, Hh, Tt * Hh);
    copy_kernel<<<(Bb * Hh + 255) / 256, 256, 0, 0>>>(
        p_hbuf, hfinal + Bb * Hh, Bb * Hh);

    // ---- logits (bf16 HMMA) ------------------------------------------------
    logits_mma_kernel<<<dim3(Vv / NT, MROWS / MT), 256, LSMEM, 0>>>(
        p_hsb, p_wob, b_out, out);

    // ---- log_softmax -------------------------------------------------------
    lse_kernel<<<MROWS, 256, 0, 0>>>(out);
    sub_kernel<<<dim3(Vv / 256, MROWS), 256, 0, 0>>>(out);
}

// round 10
// speedup vs baseline: 4.4558x; 1.3063x over previous
#include <cuda_runtime.h>
#include <cuda_bf16.h>
#include <math.h>
#include <stdint.h>

// Problem constants
#define Bb 32
#define Tt 128
#define Hh 1024
#define Ll 2
#define Vv 32000
#define H3 3072          // 3*H
#define MROWS (Tt*Bb)    // 4096
#define BOS 1
#define NBLK 128         // persistent recurrence blocks (all resident)

// Logits HMMA tiling (bf16)
#define MT 128
#define NT 128
#define KC 64            // bf16 per chunk = 128B
#define NKC (Hh / KC)    // 16
#define ATILEB (MT * 128)
#define BTILEB (NT * 128)
#define LSMEM (2 * (ATILEB + BTILEB))   // 64 KB

// gi GEMM tiling (tf32)
#define GKC 32           // fp32 per chunk = 128B
#define GNKC (Hh / GKC)  // 32
#define GTILEB (128 * 128)  // 16 KB
#define GSMEM (4 * GTILEB)  // 64 KB (A+B double buffered)

// fused log_softmax smem (one row)
#define LSMSZ (Vv * 4)   // 128000 B

// ---------------- scratch (static device globals) ---------------------------
__device__ float g_gi[MROWS * H3];
__device__ float g_h0[MROWS * Hh];
__device__ __nv_bfloat16 g_hsb[MROWS * Hh];
__device__ __nv_bfloat16 g_wob[(size_t)Vv * Hh];
__device__ float g_hbuf[2][Bb * Hh];
__device__ int   g_ids[MROWS];
__device__ unsigned g_bar;

// ---------------- PTX helpers (all arch-portable: sm_80+) --------------------
__device__ __forceinline__ uint32_t smem_u32(const void* p) {
    uint32_t a;
    asm("{ .reg .u64 t; cvta.to.shared.u64 t, %1; cvt.u32.u64 %0, t; }"
        : "=r"(a) : "l"(p));
    return a;
}
__device__ __forceinline__ void cp_async16(uint32_t s, const void* g) {
    asm volatile("cp.async.cg.shared.global [%0], [%1], 16;"
                 :: "r"(s), "l"(g) : "memory");
}
#define CP_COMMIT() asm volatile("cp.async.commit_group;" ::: "memory")
#define CP_WAIT1()  asm volatile("cp.async.wait_group 1;" ::: "memory")
#define CP_WAIT0()  asm volatile("cp.async.wait_group 0;" ::: "memory")
#define LDSM4(r, addr) \
    asm volatile("ldmatrix.sync.aligned.m8n8.x4.shared.b16 {%0,%1,%2,%3}, [%4];" \
        : "=r"((r)[0]), "=r"((r)[1]), "=r"((r)[2]), "=r"((r)[3]) : "r"(addr))
#define MMA16816(c, a, b0, b1) \
    asm volatile("mma.sync.aligned.m16n8k16.row.col.f32.bf16.bf16.f32 " \
        "{%0,%1,%2,%3}, {%4,%5,%6,%7}, {%8,%9}, {%0,%1,%2,%3};" \
        : "+f"((c)[0]), "+f"((c)[1]), "+f"((c)[2]), "+f"((c)[3]) \
        : "r"((a)[0]), "r"((a)[1]), "r"((a)[2]), "r"((a)[3]), "r"(b0), "r"(b1))
#define MMA1688TF(c, a, b0, b1) \
    asm volatile("mma.sync.aligned.m16n8k8.row.col.f32.tf32.tf32.f32 " \
        "{%0,%1,%2,%3}, {%4,%5,%6,%7}, {%8,%9}, {%0,%1,%2,%3};" \
        : "+f"((c)[0]), "+f"((c)[1]), "+f"((c)[2]), "+f"((c)[3]) \
        : "r"((a)[0]), "r"((a)[1]), "r"((a)[2]), "r"((a)[3]), "r"(b0), "r"(b1))

__device__ __forceinline__ uint32_t lds_tf32(uint32_t addr) {
    float v; uint32_t o;
    asm("ld.shared.f32 %0, [%1];" : "=f"(v) : "r"(addr));
    asm("cvt.rna.tf32.f32 %0, %1;" : "=r"(o) : "f"(v));
    return o;
}
// swizzled byte offset for fp32 tile rows of 32 floats (128B): c in floats
__device__ __forceinline__ uint32_t swz32(int r, int c) {
    return r * 128 + (((c >> 2) ^ (r & 7)) << 4) + ((c & 3) << 2);
}

// FFMA-only e^x (x <= 0 path): 2^t with degree-6 Taylor of 2^f
__device__ __forceinline__ float fast_exp(float x) {
    float t = fmaxf(x * 1.4426950408889634f, -126.0f);
    float n = floorf(t);
    float f = t - n;
    float p = 0.0001540353f;
    p = p * f + 0.0013333558f;
    p = p * f + 0.0096181291f;
    p = p * f + 0.0555041087f;
    p = p * f + 0.2402265070f;
    p = p * f + 0.6931471806f;
    p = p * f + 1.0f;
    return __int_as_float(((int)n + 127) << 23) * p;
}

// ---------------- tiny helpers ----------------------------------------------
__global__ void copy_kernel(const float* __restrict__ src, float* __restrict__ dst, int n) {
    int i = blockIdx.x * blockDim.x + threadIdx.x;
    if (i < n) dst[i] = src[i];
}
__global__ void zero_bar_kernel() { g_bar = 0u; }
__global__ void wconv_kernel(const float* __restrict__ w) {
    size_t n = (size_t)Vv * Hh;
    size_t stride = (size_t)gridDim.x * blockDim.x;
    for (size_t i = blockIdx.x * (size_t)blockDim.x + threadIdx.x; i < n; i += stride)
        g_wob[i] = __float2bfloat16(w[i]);
}
__global__ void ids_kernel(const int* __restrict__ target) {
    int i = blockIdx.x * blockDim.x + threadIdx.x;
    if (i >= MROWS) return;
    int t = i / Bb, b = i % Bb;
    g_ids[i] = (t == 0) ? BOS : target[b * Tt + (t - 1)];
}

// ---------------- persistent GRU layer (coalesced; proven in R9) -------------
__device__ __forceinline__ void reduce_group(float* v, int lane) {
    #pragma unroll
    for (int s = 16; s >= 1; s >>= 1) {
        #pragma unroll
        for (int i = 0; i < s; i++) {
            float keep = (lane & s) ? v[i + s] : v[i];
            float send = (lane & s) ? v[i] : v[i + s];
            float recv = __shfl_xor_sync(0xffffffffu, send, s);
            v[i] = keep + recv;
        }
    }
}

__global__ void __launch_bounds__(256) gru_layer_kernel(
    const float* __restrict__ gi,
    const float* __restrict__ whh,
    const float* __restrict__ bhh,
    float* __restrict__ hist,
    __nv_bfloat16* __restrict__ histb,
    int tS, int bS)
{
    __shared__ float ghS[24][33];
    const int tid  = threadIdx.x;
    const int lane = tid & 31;
    const int w    = tid >> 5;
    const int rg   = w >> 1;
    const int bg   = w & 1;
    const int j0   = blockIdx.x * 8;

    const int gb = tid >> 3;
    const int gj = tid & 7;
    const int j  = j0 + gj;
    const float bhr = bhh[j];
    const float bhz = bhh[Hh + j];
    const float bhn = bhh[2 * Hh + j];

    for (int t = 0; t < Tt; t++) {
        const float* __restrict__ hcur = g_hbuf[t & 1];
        float* __restrict__ hnxt = g_hbuf[(t + 1) & 1];

        float acc[96];
        #pragma unroll
        for (int i = 0; i < 96; i++) acc[i] = 0.f;

        for (int i8 = 0; i8 < 8; i8++) {
            const int k0 = i8 * 128 + lane * 4;
            float4 hv[16];
            #pragma unroll
            for (int b = 0; b < 16; b++)
                hv[b] = *(const float4*)(hcur + (size_t)(bg * 16 + b) * Hh + k0);
            #pragma unroll
            for (int q = 0; q < 6; q++) {
                int rid = rg * 6 + q;
                int wrow = (rid >> 3) * Hh + j0 + (rid & 7);
                float4 wv = *(const float4*)(whh + (size_t)wrow * Hh + k0);
                #pragma unroll
                for (int b = 0; b < 16; b++) {
                    acc[q * 16 + b] += wv.x * hv[b].x;
                    acc[q * 16 + b] += wv.y * hv[b].y;
                    acc[q * 16 + b] += wv.z * hv[b].z;
                    acc[q * 16 + b] += wv.w * hv[b].w;
                }
            }
        }
        reduce_group(acc, lane);
        reduce_group(acc + 32, lane);
        reduce_group(acc + 64, lane);
        #pragma unroll
        for (int g3 = 0; g3 < 3; g3++) {
            int flat = g3 * 32 + lane;
            int q = flat >> 4, bcol = flat & 15;
            int rid = rg * 6 + q;
            ghS[rid][bg * 16 + bcol] = acc[g3 * 32];
        }
        __syncthreads();

        {
            const float* git = gi + ((size_t)t * Bb + gb) * H3;
            float ghr = ghS[gj][gb] + bhr;
            float ghz = ghS[8 + gj][gb] + bhz;
            float ghn = ghS[16 + gj][gb] + bhn;
            float r_ = 1.f / (1.f + expf(-(git[j] + ghr)));
            float z_ = 1.f / (1.f + expf(-(git[Hh + j] + ghz)));
            float n_ = tanhf(git[2 * Hh + j] + r_ * ghn);
            float hp = hcur[(size_t)gb * Hh + j];
            float hn = (1.f - z_) * n_ + z_ * hp;
            size_t oidx = (size_t)t * tS + (size_t)gb * bS + j;
            if (histb) histb[oidx] = __float2bfloat16(hn);
            else       hist[oidx] = hn;
            hnxt[(size_t)gb * Hh + j] = hn;
        }

        __threadfence();
        __syncthreads();
        if (tid == 0) {
            atomicAdd(&g_bar, 1u);
            unsigned tgt = (unsigned)(NBLK * (t + 1));
            volatile unsigned* vb = &g_bar;
            while (*vb < tgt) { __nanosleep(32); }
        }
        __syncthreads();
        __threadfence();
    }
}

// ---------------- tf32 gi GEMM: C[m][n] = A/emb @ W^T + bias -----------------
// Block 128x128, 8 warps (64Mx32N), GKC=32 fp32 chunks, 2-stage cp.async,
// 128B swizzled rows; fragments via conflict-free ld.shared.f32 + cvt.rna.tf32.
#define GPREF(ch, p) do {                                                       \
    int _k0 = (ch) * GKC;                                                       \
    uint32_t _ab = sb + (p) * GTILEB;                                           \
    uint32_t _bb = sb + 2 * GTILEB + (p) * GTILEB;                              \
    _Pragma("unroll")                                                           \
    for (int _it = 0; _it < 4; _it++) {                                         \
        int _idx = _it * 256 + tid, _row = _idx >> 3, _c = _idx & 7;            \
        const float* _as = GATHER                                               \
            ? emb + (size_t)g_ids[m0 + _row] * Hh + _k0 + _c * 4                \
            : A + (size_t)(m0 + _row) * Hh + _k0 + _c * 4;                      \
        cp_async16(_ab + _row * 128 + ((_c ^ (_row & 7)) * 16), _as);           \
        cp_async16(_bb + _row * 128 + ((_c ^ (_row & 7)) * 16),                 \
                   W + (size_t)(n0 + _row) * Hh + _k0 + _c * 4);                \
    }                                                                           \
    CP_COMMIT();                                                                \
} while (0)

template<int GATHER>
__global__ void __launch_bounds__(256) gi_mma_kernel(
    const float* __restrict__ A, const float* __restrict__ W,
    const float* __restrict__ bias, float* __restrict__ C,
    const float* __restrict__ emb)
{
    extern __shared__ char smem[];
    const int tid  = threadIdx.x;
    const int lane = tid & 31;
    const int warp = tid >> 5;
    const int m0 = blockIdx.y * 128;
    const int n0 = blockIdx.x * 128;
    const int wm = (warp & 1) * 64;
    const int wn = (warp >> 1) * 32;
    uint32_t sb = smem_u32(smem);

    float acc[4][4][4];
    #pragma unroll
    for (int i = 0; i < 4; i++)
        #pragma unroll
        for (int jj = 0; jj < 4; jj++)
            #pragma unroll
            for (int k = 0; k < 4; k++) acc[i][jj][k] = 0.f;

    GPREF(0, 0);
    for (int ch = 0; ch < GNKC; ch++) {
        const int p = ch & 1;
        if (ch + 1 < GNKC) { GPREF(ch + 1, (ch + 1) & 1); CP_WAIT1(); }
        else               { CP_WAIT0(); }
        __syncthreads();

        const uint32_t ab = sb + p * GTILEB;
        const uint32_t bb = sb + 2 * GTILEB + p * GTILEB;
        #pragma unroll
        for (int k8 = 0; k8 < 4; k8++) {
            uint32_t a[4][4], b[4][2];
            #pragma unroll
            for (int mf = 0; mf < 4; mf++) {
                int r = wm + mf * 16 + (lane >> 2);
                int c = k8 * 8 + (lane & 3);
                a[mf][0] = lds_tf32(ab + swz32(r, c));
                a[mf][1] = lds_tf32(ab + swz32(r + 8, c));
                a[mf][2] = lds_tf32(ab + swz32(r, c + 4));
                a[mf][3] = lds_tf32(ab + swz32(r + 8, c + 4));
            }
            #pragma unroll
            for (int nf = 0; nf < 4; nf++) {
                int rn = wn + nf * 8 + (lane >> 2);
                int ck = k8 * 8 + (lane & 3);
                b[nf][0] = lds_tf32(bb + swz32(rn, ck));
                b[nf][1] = lds_tf32(bb + swz32(rn, ck + 4));
            }
            #pragma unroll
            for (int mf = 0; mf < 4; mf++)
                #pragma unroll
                for (int nf = 0; nf < 4; nf++)
                    MMA1688TF(acc[mf][nf], a[mf], b[nf][0], b[nf][1]);
        }
        __syncthreads();
    }

    #pragma unroll
    for (int mf = 0; mf < 4; mf++) {
        #pragma unroll
        for (int nf = 0; nf < 4; nf++) {
            int r  = m0 + wm + mf * 16 + (lane >> 2);
            int cg = n0 + wn + nf * 8 + (lane & 3) * 2;
            float b0 = bias[cg], b1 = bias[cg + 1];
            float2 v0 = make_float2(acc[mf][nf][0] + b0, acc[mf][nf][1] + b1);
            float2 v1 = make_float2(acc[mf][nf][2] + b0, acc[mf][nf][3] + b1);
            *(float2*)(C + (size_t)r * H3 + cg) = v0;
            *(float2*)(C + (size_t)(r + 8) * H3 + cg) = v1;
        }
    }
}

// ---------------- bf16 HMMA logits GEMM (proven in R9) -----------------------
#define PREF(ch, p) do {                                                        \
    int _k0 = (ch) * KC;                                                        \
    uint32_t _ab = sb + (p) * ATILEB;                                           \
    uint32_t _bb = sb + 2 * ATILEB + (p) * BTILEB;                              \
    _Pragma("unroll")                                                           \
    for (int _it = 0; _it < 4; _it++) {                                         \
        int _idx = _it * 256 + tid, _row = _idx >> 3, _c = _idx & 7;            \
        cp_async16(_ab + _row * 128 + ((_c ^ (_row & 7)) * 16),                 \
                   hsb + (size_t)(m0 + _row) * Hh + _k0 + _c * 8);              \
        cp_async16(_bb + _row * 128 + ((_c ^ (_row & 7)) * 16),                 \
                   wob + (size_t)(n0 + _row) * Hh + _k0 + _c * 8);              \
    }                                                                           \
    CP_COMMIT();                                                                \
} while (0)

__global__ void __launch_bounds__(256) logits_mma_kernel(
    const __nv_bfloat16* __restrict__ hsb,
    const __nv_bfloat16* __restrict__ wob,
    const float* __restrict__ bias,
    float* __restrict__ out)
{
    extern __shared__ char smem[];
    const int tid  = threadIdx.x;
    const int lane = tid & 31;
    const int warp = tid >> 5;
    const int m0 = blockIdx.y * MT;
    const int n0 = blockIdx.x * NT;
    const int wm = (warp & 1) * 64;
    const int wn = (warp >> 1) * 32;
    uint32_t sb = smem_u32(smem);

    float acc[4][4][4];
    #pragma unroll
    for (int i = 0; i < 4; i++)
        #pragma unroll
        for (int jj = 0; jj < 4; jj++)
            #pragma unroll
            for (int k = 0; k < 4; k++) acc[i][jj][k] = 0.f;

    PREF(0, 0);
    for (int ch = 0; ch < NKC; ch++) {
        const int p = ch & 1;
        if (ch + 1 < NKC) { PREF(ch + 1, (ch + 1) & 1); CP_WAIT1(); }
        else              { CP_WAIT0(); }
        __syncthreads();

        const uint32_t ab = sb + p * ATILEB;
        const uint32_t bb = sb + 2 * ATILEB + p * BTILEB;
        #pragma unroll
        for (int k16 = 0; k16 < 4; k16++) {
            uint32_t a[4][4], b[2][4];
            #pragma unroll
            for (int mf = 0; mf < 4; mf++) {
                int row = wm + mf * 16 + (lane & 7) + ((lane >> 3) & 1) * 8;
                int c = k16 * 2 + (lane >> 4);
                LDSM4(a[mf], ab + row * 128 + ((c ^ (row & 7)) * 16));
            }
            #pragma unroll
            for (int nf2 = 0; nf2 < 2; nf2++) {
                int row = wn + nf2 * 16 + (lane & 7) + ((lane >> 4) & 1) * 8;
                int c = k16 * 2 + ((lane >> 3) & 1);
                LDSM4(b[nf2], bb + row * 128 + ((c ^ (row & 7)) * 16));
            }
            #pragma unroll
            for (int mf = 0; mf < 4; mf++)
                #pragma unroll
                for (int nf = 0; nf < 4; nf++)
                    MMA16816(acc[mf][nf], a[mf],
                             b[nf >> 1][(nf & 1) * 2], b[nf >> 1][(nf & 1) * 2 + 1]);
        }
        __syncthreads();
    }

    #pragma unroll
    for (int mf = 0; mf < 4; mf++) {
        #pragma unroll
        for (int nf = 0; nf < 4; nf++) {
            int r  = m0 + wm + mf * 16 + (lane >> 2);
            int cg = n0 + wn + nf * 8 + (lane & 3) * 2;
            float b0 = bias[cg], b1 = bias[cg + 1];
            float2 v0 = make_float2(acc[mf][nf][0] + b0, acc[mf][nf][1] + b1);
            float2 v1 = make_float2(acc[mf][nf][2] + b0, acc[mf][nf][3] + b1);
            *(float2*)(out + (size_t)r * Vv + cg) = v0;
            *(float2*)(out + (size_t)(r + 8) * Vv + cg) = v1;
        }
    }
}

// ---------------- fused log_softmax (smem-resident row, FFMA exp) ------------
__global__ void lsm_kernel(float* __restrict__ out) {
    extern __shared__ float rowbuf[];   // Vv floats (128 KB)
    __shared__ float warpred[8];
    __shared__ float s_bcast;
    const int tid = threadIdx.x;
    const int lane = tid & 31, wid = tid >> 5;
    float* p = out + (size_t)blockIdx.x * Vv;

    // pass 1: gmem -> smem, running max
    float mx = -1e30f;
    for (int i = tid; i < Vv / 4; i += 256) {
        float4 v = *(const float4*)(p + i * 4);
        *(float4*)(rowbuf + i * 4) = v;
        mx = fmaxf(mx, fmaxf(fmaxf(v.x, v.y), fmaxf(v.z, v.w)));
    }
    #pragma unroll
    for (int s = 16; s > 0; s >>= 1)
        mx = fmaxf(mx, __shfl_xor_sync(0xffffffffu, mx, s));
    if (lane == 0) warpred[wid] = mx;
    __syncthreads();
    mx = warpred[lane & 7];
    #pragma unroll
    for (int s = 4; s > 0; s >>= 1)
        mx = fmaxf(mx, __shfl_xor_sync(0xffffffffu, mx, s));
    mx = __shfl_sync(0xffffffffu, mx, 0);

    // pass 2: sum of exp from smem (FFMA-poly exp; no MUFU)
    float sum = 0.f;
    for (int i = tid; i < Vv; i += 256) sum += fast_exp(rowbuf[i] - mx);
    #pragma unroll
    for (int s = 16; s > 0; s >>= 1)
        sum += __shfl_xor_sync(0xffffffffu, sum, s);
    __syncthreads();
    if (lane == 0) warpred[wid] = sum;
    __syncthreads();
    if (tid == 0) {
        float tot = 0.f;
        #pragma unroll
        for (int w = 0; w < 8; w++) tot += warpred[w];
        s_bcast = mx + logf(tot);
    }
    __syncthreads();
    float lse = s_bcast;

    // pass 3: smem -> gmem, subtracted
    for (int i = tid; i < Vv / 4; i += 256) {
        float4 v = *(const float4*)(rowbuf + i * 4);
        v.x -= lse; v.y -= lse; v.z -= lse; v.w -= lse;
        *(float4*)(p + i * 4) = v;
    }
}

// ---------------- host driver ------------------------------------------------
extern "C" void kernel_launch(void* const* d_in, const int* in_sizes, int n_in,
                              void* d_out, int out_size) {
    const float* enc_h  = (const float*)d_in[1];
    const int*   target = (const int*)  d_in[2];
    const float* emb    = (const float*)d_in[3];
    const float* w_ih   = (const float*)d_in[4];
    const float* w_hh   = (const float*)d_in[5];
    const float* b_ih   = (const float*)d_in[6];
    const float* b_hh   = (const float*)d_in[7];
    const float* w_out  = (const float*)d_in[8];
    const float* b_out  = (const float*)d_in[9];
    float* out = (float*)d_out;

    float *p_gi, *p_h0, *p_hbuf;
    __nv_bfloat16 *p_hsb, *p_wob;
    cudaGetSymbolAddress((void**)&p_gi,   g_gi);
    cudaGetSymbolAddress((void**)&p_h0,   g_h0);
    cudaGetSymbolAddress((void**)&p_hsb,  g_hsb);
    cudaGetSymbolAddress((void**)&p_wob,  g_wob);
    cudaGetSymbolAddress((void**)&p_hbuf, g_hbuf);

    float* hfinal = out + (size_t)MROWS * Vv;

    cudaFuncSetAttribute(logits_mma_kernel,
                         cudaFuncAttributeMaxDynamicSharedMemorySize, LSMEM);
    cudaFuncSetAttribute(gi_mma_kernel<0>,
                         cudaFuncAttributeMaxDynamicSharedMemorySize, GSMEM);
    cudaFuncSetAttribute(gi_mma_kernel<1>,
                         cudaFuncAttributeMaxDynamicSharedMemorySize, GSMEM);
    cudaFuncSetAttribute(lsm_kernel,
                         cudaFuncAttributeMaxDynamicSharedMemorySize, LSMSZ);

    // prep
    ids_kernel<<<(MROWS + 255) / 256, 256, 0, 0>>>(target);
    wconv_kernel<<<4096, 256, 0, 0>>>(w_out);

    // ---- layer 0 -----------------------------------------------------------
    gi_mma_kernel<1><<<dim3(H3 / 128, MROWS / 128), 256, GSMEM, 0>>>(
        nullptr, w_ih, b_ih, p_gi, emb);
    copy_kernel<<<(Bb * Hh + 255) / 256, 256, 0, 0>>>(enc_h, p_hbuf, Bb * Hh);
    zero_bar_kernel<<<1, 1, 0, 0>>>();
    gru_layer_kernel<<<NBLK, 256, 0, 0>>>(
        p_gi, w_hh, b_hh, p_h0, nullptr, Bb * Hh, Hh);
    copy_kernel<<<(Bb * Hh + 255) / 256, 256, 0, 0>>>(p_hbuf, hfinal, Bb * Hh);

    // ---- layer 1 -----------------------------------------------------------
    gi_mma_kernel<0><<<dim3(H3 / 128, MROWS / 128), 256, GSMEM, 0>>>(
        p_h0, w_ih + (size_t)H3 * Hh, b_ih + H3, p_gi, nullptr);
    copy_kernel<<<(Bb * Hh + 255) / 256, 256, 0, 0>>>(
        enc_h + Bb * Hh, p_hbuf, Bb * Hh);
    zero_bar_kernel<<<1, 1, 0, 0>>>();
    gru_layer_kernel<<<NBLK, 256, 0, 0>>>(
        p_gi, w_hh + (size_t)H3 * Hh, b_hh + H3, nullptr, p_hsb, Hh, Tt * Hh);
    copy_kernel<<<(Bb * Hh + 255) / 256, 256, 0, 0>>>(
        p_hbuf, hfinal + Bb * Hh, Bb * Hh);

    // ---- logits (bf16 HMMA) ------------------------------------------------
    logits_mma_kernel<<<dim3(Vv / NT, MROWS / MT), 256, LSMEM, 0>>>(
        p_hsb, p_wob, b_out, out);

    // ---- fused log_softmax -------------------------------------------------
    lsm_kernel<<<MROWS, 256, LSMSZ, 0>>>(out);
}

// round 11
// speedup vs baseline: 6.2782x; 1.4090x over previous
#include <cuda_runtime.h>
#include <cuda_bf16.h>
#include <math.h>
#include <stdint.h>

// Problem constants
#define Bb 32
#define Tt 128
#define Hh 1024
#define Ll 2
#define Vv 32000
#define H3 3072          // 3*H
#define MROWS (Tt*Bb)    // 4096
#define BOS 1
#define NBLK 128         // persistent recurrence blocks (all resident)

// Logits HMMA tiling (bf16)
#define MT 128
#define NT 128
#define KC 64
#define NKC (Hh / KC)
#define ATILEB (MT * 128)
#define BTILEB (NT * 128)
#define LSMEM (2 * (ATILEB + BTILEB))   // 64 KB

// gi GEMM tiling (tf32)
#define GKC 32
#define GNKC (Hh / GKC)
#define GTILEB (128 * 128)
#define GSMEM (4 * GTILEB)              // 64 KB

// GRU smem: A(h) 32x1024 fp32 = 128KB, B(whh slice tf32) 24x1024 = 96KB
#define GRUSM (32 * 4096 + 24 * 4096)   // 229376 B (<= 232448 cap)

// fused log_softmax smem (one row)
#define LSMSZ (Vv * 4)

// ---------------- scratch (static device globals) ---------------------------
__device__ float g_gi[MROWS * H3];
__device__ float g_h0[MROWS * Hh];
__device__ __nv_bfloat16 g_hsb[MROWS * Hh];
__device__ __nv_bfloat16 g_wob[(size_t)Vv * Hh];
__device__ float g_hbuf[2][Bb * Hh];
__device__ int   g_ids[MROWS];
__device__ unsigned g_bar;

// ---------------- PTX helpers (all arch-portable: sm_80+) --------------------
__device__ __forceinline__ uint32_t smem_u32(const void* p) {
    uint32_t a;
    asm("{ .reg .u64 t; cvta.to.shared.u64 t, %1; cvt.u32.u64 %0, t; }"
        : "=r"(a) : "l"(p));
    return a;
}
__device__ __forceinline__ void cp_async16(uint32_t s, const void* g) {
    asm volatile("cp.async.cg.shared.global [%0], [%1], 16;"
                 :: "r"(s), "l"(g) : "memory");
}
#define CP_COMMIT() asm volatile("cp.async.commit_group;" ::: "memory")
#define CP_WAIT1()  asm volatile("cp.async.wait_group 1;" ::: "memory")
#define CP_WAIT0()  asm volatile("cp.async.wait_group 0;" ::: "memory")
#define LDSM4(r, addr) \
    asm volatile("ldmatrix.sync.aligned.m8n8.x4.shared.b16 {%0,%1,%2,%3}, [%4];" \
        : "=r"((r)[0]), "=r"((r)[1]), "=r"((r)[2]), "=r"((r)[3]) : "r"(addr))
#define MMA16816(c, a, b0, b1) \
    asm volatile("mma.sync.aligned.m16n8k16.row.col.f32.bf16.bf16.f32 " \
        "{%0,%1,%2,%3}, {%4,%5,%6,%7}, {%8,%9}, {%0,%1,%2,%3};" \
        : "+f"((c)[0]), "+f"((c)[1]), "+f"((c)[2]), "+f"((c)[3]) \
        : "r"((a)[0]), "r"((a)[1]), "r"((a)[2]), "r"((a)[3]), "r"(b0), "r"(b1))
#define MMA1688TF(c, a, b0, b1) \
    asm volatile("mma.sync.aligned.m16n8k8.row.col.f32.tf32.tf32.f32 " \
        "{%0,%1,%2,%3}, {%4,%5,%6,%7}, {%8,%9}, {%0,%1,%2,%3};" \
        : "+f"((c)[0]), "+f"((c)[1]), "+f"((c)[2]), "+f"((c)[3]) \
        : "r"((a)[0]), "r"((a)[1]), "r"((a)[2]), "r"((a)[3]), "r"(b0), "r"(b1))

__device__ __forceinline__ uint32_t lds_tf32(uint32_t addr) {
    float v; uint32_t o;
    asm("ld.shared.f32 %0, [%1];" : "=f"(v) : "r"(addr));
    asm("cvt.rna.tf32.f32 %0, %1;" : "=r"(o) : "f"(v));
    return o;
}
__device__ __forceinline__ uint32_t lds_u32(uint32_t addr) {
    uint32_t v;
    asm("ld.shared.b32 %0, [%1];" : "=r"(v) : "r"(addr));
    return v;
}
__device__ __forceinline__ uint32_t f2tf(float v) {
    uint32_t o;
    asm("cvt.rna.tf32.f32 %0, %1;" : "=r"(o) : "f"(v));
    return o;
}
// swizzle for 32-float (128B) rows
__device__ __forceinline__ uint32_t swz32(int r, int c) {
    return r * 128 + (((c >> 2) ^ (r & 7)) << 4) + ((c & 3) << 2);
}
// swizzle for 1024-float (4KB) rows
__device__ __forceinline__ uint32_t swzH(int r, int c) {
    return r * 4096 + ((((c >> 2) ^ (r & 7)) & 0xFFFF) << 4) + ((c & 3) << 2);
}

// FFMA-only e^x
__device__ __forceinline__ float fast_exp(float x) {
    float t = fmaxf(x * 1.4426950408889634f, -126.0f);
    float n = floorf(t);
    float f = t - n;
    float p = 0.0001540353f;
    p = p * f + 0.0013333558f;
    p = p * f + 0.0096181291f;
    p = p * f + 0.0555041087f;
    p = p * f + 0.2402265070f;
    p = p * f + 0.6931471806f;
    p = p * f + 1.0f;
    return __int_as_float(((int)n + 127) << 23) * p;
}

// ---------------- tiny helpers ----------------------------------------------
__global__ void copy_kernel(const float* __restrict__ src, float* __restrict__ dst, int n) {
    int i = blockIdx.x * blockDim.x + threadIdx.x;
    if (i < n) dst[i] = src[i];
}
__global__ void zero_bar_kernel() { g_bar = 0u; }
__global__ void wconv_kernel(const float* __restrict__ w) {
    size_t n = (size_t)Vv * Hh;
    size_t stride = (size_t)gridDim.x * blockDim.x;
    for (size_t i = blockIdx.x * (size_t)blockDim.x + threadIdx.x; i < n; i += stride)
        g_wob[i] = __float2bfloat16(w[i]);
}
__global__ void ids_kernel(const int* __restrict__ target) {
    int i = blockIdx.x * blockDim.x + threadIdx.x;
    if (i >= MROWS) return;
    int t = i / Bb, b = i % Bb;
    g_ids[i] = (t == 0) ? BOS : target[b * Tt + (t - 1)];
}

// ---------------- persistent GRU layer: tf32 HMMA recurrence -----------------
// 128 blocks x 256 thr (1/SM, all resident). Block owns 8 h-cols j0..j0+7 =
// 24 whh rows (3 gates x 8), staged ONCE in smem as tf32. Per step: stage h
// [32][1024] via cp.async (swizzled), warps K-split 8x128, m16n8k8 tf32 MMA,
// 8-way cross-warp reduce through smem (aliased into dead A region), gate
// math, ping-pong h, grid barrier.
__global__ void __launch_bounds__(256) gru_layer_kernel(
    const float* __restrict__ gi,     // [T][B][3H]
    const float* __restrict__ whh,    // [3H][H]
    const float* __restrict__ bhh,    // [3H]
    float* __restrict__ hist,         // fp32 history (or null)
    __nv_bfloat16* __restrict__ histb,// bf16 history (or null)
    float* __restrict__ hfin,         // final h destination [B][H]
    int tS, int bS)
{
    extern __shared__ float smf[];
    float* part = smf;                 // [8][792] aliased into A region
    float* ghS  = smf + 6400;          // [24*33]  aliased into A region
    const uint32_t aBase = smem_u32(smf);
    const uint32_t bBase = aBase + 32 * 4096;

    const int tid  = threadIdx.x;
    const int lane = tid & 31;
    const int w    = tid >> 5;
    const int j0   = blockIdx.x * 8;

    const int gb = tid >> 3;          // gate-math batch 0..31
    const int gj = tid & 7;           // gate-math col 0..7
    const int j  = j0 + gj;
    const float bhr = bhh[j];
    const float bhz = bhh[Hh + j];
    const float bhn = bhh[2 * Hh + j];

    // ---- stage whh slice (24 rows) into smem, pre-converted to tf32 --------
    for (int idx = tid; idx < 24 * 256; idx += 256) {
        int n = idx >> 8, c = idx & 255;
        int grow = (n >> 3) * Hh + j0 + (n & 7);
        float4 v = *(const float4*)(whh + (size_t)grow * Hh + c * 4);
        uint4 o = make_uint4(f2tf(v.x), f2tf(v.y), f2tf(v.z), f2tf(v.w));
        *(uint4*)((char*)smf + (bBase - aBase) + n * 4096 + (((c ^ (n & 7)) & 0xFFFF) << 4)) = o;
    }
    __syncthreads();

    for (int t = 0; t < Tt; t++) {
        const float* __restrict__ hcur = g_hbuf[t & 1];
        float* __restrict__ hnxt = g_hbuf[(t + 1) & 1];

        // ---- stage h [32][1024] via cp.async, swizzled ----------------------
        for (int i = tid; i < 8192; i += 256) {
            int row = i >> 8, c = i & 255;
            cp_async16(aBase + row * 4096 + (((c ^ (row & 7)) & 0xFFFF) << 4),
                       hcur + (size_t)row * Hh + c * 4);
        }
        CP_COMMIT();
        CP_WAIT0();
        __syncthreads();

        // ---- tf32 MMA: warp w covers k in [w*128, w*128+128) ---------------
        float acc[2][3][4];
        #pragma unroll
        for (int m = 0; m < 2; m++)
            #pragma unroll
            for (int nf = 0; nf < 3; nf++)
                #pragma unroll
                for (int q = 0; q < 4; q++) acc[m][nf][q] = 0.f;

        const int k0w = w * 128;
        #pragma unroll
        for (int k8 = 0; k8 < 16; k8++) {
            const int k0 = k0w + k8 * 8;
            const int cA = k0 + (lane & 3);
            uint32_t a[2][4], b[3][2];
            #pragma unroll
            for (int m = 0; m < 2; m++) {
                int r = m * 16 + (lane >> 2);
                a[m][0] = lds_tf32(aBase + swzH(r, cA));
                a[m][1] = lds_tf32(aBase + swzH(r + 8, cA));
                a[m][2] = lds_tf32(aBase + swzH(r, cA + 4));
                a[m][3] = lds_tf32(aBase + swzH(r + 8, cA + 4));
            }
            #pragma unroll
            for (int nf = 0; nf < 3; nf++) {
                int rn = nf * 8 + (lane >> 2);
                b[nf][0] = lds_u32(bBase + swzH(rn, cA));
                b[nf][1] = lds_u32(bBase + swzH(rn, cA + 4));
            }
            #pragma unroll
            for (int m = 0; m < 2; m++)
                #pragma unroll
                for (int nf = 0; nf < 3; nf++)
                    MMA1688TF(acc[m][nf], a[m], b[nf][0], b[nf][1]);
        }
        __syncthreads();   // all MMA reads of A done before aliased writes

        // ---- write partials: part[w][n*33 + m] ------------------------------
        #pragma unroll
        for (int m = 0; m < 2; m++) {
            #pragma unroll
            for (int nf = 0; nf < 3; nf++) {
                int rowm = m * 16 + (lane >> 2);
                int col = nf * 8 + 2 * (lane & 3);
                float* pw = part + w * 792;
                pw[col * 33 + rowm]           = acc[m][nf][0];
                pw[(col + 1) * 33 + rowm]     = acc[m][nf][1];
                pw[col * 33 + rowm + 8]       = acc[m][nf][2];
                pw[(col + 1) * 33 + rowm + 8] = acc[m][nf][3];
            }
        }
        __syncthreads();

        // ---- 8-way reduce -> ghS[n*33 + m] ----------------------------------
        #pragma unroll
        for (int rep = 0; rep < 3; rep++) {
            int p = rep * 256 + tid;          // p = n*32 + m
            int n = p >> 5, m = p & 31;
            float s = 0.f;
            #pragma unroll
            for (int ww = 0; ww < 8; ww++) s += part[ww * 792 + n * 33 + m];
            ghS[n * 33 + m] = s;
        }
        __syncthreads();

        // ---- gate math for owned (gb, j) ------------------------------------
        {
            const float* git = gi + ((size_t)t * Bb + gb) * H3;
            float ghr = ghS[gj * 33 + gb] + bhr;
            float ghz = ghS[(8 + gj) * 33 + gb] + bhz;
            float ghn = ghS[(16 + gj) * 33 + gb] + bhn;
            float r_ = 1.f / (1.f + expf(-(git[j] + ghr)));
            float z_ = 1.f / (1.f + expf(-(git[Hh + j] + ghz)));
            float n_ = tanhf(git[2 * Hh + j] + r_ * ghn);
            float hp = hcur[(size_t)gb * Hh + j];
            float hn = (1.f - z_) * n_ + z_ * hp;
            size_t oidx = (size_t)t * tS + (size_t)gb * bS + j;
            if (histb) histb[oidx] = __float2bfloat16(hn);
            else       hist[oidx] = hn;
            hnxt[(size_t)gb * Hh + j] = hn;
            if (t == Tt - 1) hfin[(size_t)gb * Hh + j] = hn;
        }

        // ---- grid barrier ----------------------------------------------------
        __threadfence();
        __syncthreads();
        if (tid == 0) {
            atomicAdd(&g_bar, 1u);
            unsigned tgt = (unsigned)(NBLK * (t + 1));
            volatile unsigned* vb = &g_bar;
            while (*vb < tgt) { __nanosleep(32); }
        }
        __syncthreads();
        __threadfence();
    }
}

// ---------------- tf32 gi GEMM (proven R10) ----------------------------------
#define GPREF(ch, p) do {                                                       \
    int _k0 = (ch) * GKC;                                                       \
    uint32_t _ab = sb + (p) * GTILEB;                                           \
    uint32_t _bb = sb + 2 * GTILEB + (p) * GTILEB;                              \
    _Pragma("unroll")                                                           \
    for (int _it = 0; _it < 4; _it++) {                                         \
        int _idx = _it * 256 + tid, _row = _idx >> 3, _c = _idx & 7;            \
        const float* _as = GATHER                                               \
            ? emb + (size_t)g_ids[m0 + _row] * Hh + _k0 + _c * 4                \
            : A + (size_t)(m0 + _row) * Hh + _k0 + _c * 4;                      \
        cp_async16(_ab + _row * 128 + ((_c ^ (_row & 7)) * 16), _as);           \
        cp_async16(_bb + _row * 128 + ((_c ^ (_row & 7)) * 16),                 \
                   W + (size_t)(n0 + _row) * Hh + _k0 + _c * 4);                \
    }                                                                           \
    CP_COMMIT();                                                                \
} while (0)

template<int GATHER>
__global__ void __launch_bounds__(256) gi_mma_kernel(
    const float* __restrict__ A, const float* __restrict__ W,
    const float* __restrict__ bias, float* __restrict__ C,
    const float* __restrict__ emb)
{
    extern __shared__ char smem[];
    const int tid  = threadIdx.x;
    const int lane = tid & 31;
    const int warp = tid >> 5;
    const int m0 = blockIdx.y * 128;
    const int n0 = blockIdx.x * 128;
    const int wm = (warp & 1) * 64;
    const int wn = (warp >> 1) * 32;
    uint32_t sb = smem_u32(smem);

    float acc[4][4][4];
    #pragma unroll
    for (int i = 0; i < 4; i++)
        #pragma unroll
        for (int jj = 0; jj < 4; jj++)
            #pragma unroll
            for (int k = 0; k < 4; k++) acc[i][jj][k] = 0.f;

    GPREF(0, 0);
    for (int ch = 0; ch < GNKC; ch++) {
        const int p = ch & 1;
        if (ch + 1 < GNKC) { GPREF(ch + 1, (ch + 1) & 1); CP_WAIT1(); }
        else               { CP_WAIT0(); }
        __syncthreads();

        const uint32_t ab = sb + p * GTILEB;
        const uint32_t bb = sb + 2 * GTILEB + p * GTILEB;
        #pragma unroll
        for (int k8 = 0; k8 < 4; k8++) {
            uint32_t a[4][4], b[4][2];
            #pragma unroll
            for (int mf = 0; mf < 4; mf++) {
                int r = wm + mf * 16 + (lane >> 2);
                int c = k8 * 8 + (lane & 3);
                a[mf][0] = lds_tf32(ab + swz32(r, c));
                a[mf][1] = lds_tf32(ab + swz32(r + 8, c));
                a[mf][2] = lds_tf32(ab + swz32(r, c + 4));
                a[mf][3] = lds_tf32(ab + swz32(r + 8, c + 4));
            }
            #pragma unroll
            for (int nf = 0; nf < 4; nf++) {
                int rn = wn + nf * 8 + (lane >> 2);
                int ck = k8 * 8 + (lane & 3);
                b[nf][0] = lds_tf32(bb + swz32(rn, ck));
                b[nf][1] = lds_tf32(bb + swz32(rn, ck + 4));
            }
            #pragma unroll
            for (int mf = 0; mf < 4; mf++)
                #pragma unroll
                for (int nf = 0; nf < 4; nf++)
                    MMA1688TF(acc[mf][nf], a[mf], b[nf][0], b[nf][1]);
        }
        __syncthreads();
    }

    #pragma unroll
    for (int mf = 0; mf < 4; mf++) {
        #pragma unroll
        for (int nf = 0; nf < 4; nf++) {
            int r  = m0 + wm + mf * 16 + (lane >> 2);
            int cg = n0 + wn + nf * 8 + (lane & 3) * 2;
            float b0 = bias[cg], b1 = bias[cg + 1];
            float2 v0 = make_float2(acc[mf][nf][0] + b0, acc[mf][nf][1] + b1);
            float2 v1 = make_float2(acc[mf][nf][2] + b0, acc[mf][nf][3] + b1);
            *(float2*)(C + (size_t)r * H3 + cg) = v0;
            *(float2*)(C + (size_t)(r + 8) * H3 + cg) = v1;
        }
    }
}

// ---------------- bf16 HMMA logits GEMM (proven R9) --------------------------
#define PREF(ch, p) do {                                                        \
    int _k0 = (ch) * KC;                                                        \
    uint32_t _ab = sb + (p) * ATILEB;                                           \
    uint32_t _bb = sb + 2 * ATILEB + (p) * BTILEB;                              \
    _Pragma("unroll")                                                           \
    for (int _it = 0; _it < 4; _it++) {                                         \
        int _idx = _it * 256 + tid, _row = _idx >> 3, _c = _idx & 7;            \
        cp_async16(_ab + _row * 128 + ((_c ^ (_row & 7)) * 16),                 \
                   hsb + (size_t)(m0 + _row) * Hh + _k0 + _c * 8);              \
        cp_async16(_bb + _row * 128 + ((_c ^ (_row & 7)) * 16),                 \
                   wob + (size_t)(n0 + _row) * Hh + _k0 + _c * 8);              \
    }                                                                           \
    CP_COMMIT();                                                                \
} while (0)

__global__ void __launch_bounds__(256) logits_mma_kernel(
    const __nv_bfloat16* __restrict__ hsb,
    const __nv_bfloat16* __restrict__ wob,
    const float* __restrict__ bias,
    float* __restrict__ out)
{
    extern __shared__ char smem[];
    const int tid  = threadIdx.x;
    const int lane = tid & 31;
    const int warp = tid >> 5;
    const int m0 = blockIdx.y * MT;
    const int n0 = blockIdx.x * NT;
    const int wm = (warp & 1) * 64;
    const int wn = (warp >> 1) * 32;
    uint32_t sb = smem_u32(smem);

    float acc[4][4][4];
    #pragma unroll
    for (int i = 0; i < 4; i++)
        #pragma unroll
        for (int jj = 0; jj < 4; jj++)
            #pragma unroll
            for (int k = 0; k < 4; k++) acc[i][jj][k] = 0.f;

    PREF(0, 0);
    for (int ch = 0; ch < NKC; ch++) {
        const int p = ch & 1;
        if (ch + 1 < NKC) { PREF(ch + 1, (ch + 1) & 1); CP_WAIT1(); }
        else              { CP_WAIT0(); }
        __syncthreads();

        const uint32_t ab = sb + p * ATILEB;
        const uint32_t bb = sb + 2 * ATILEB + p * BTILEB;
        #pragma unroll
        for (int k16 = 0; k16 < 4; k16++) {
            uint32_t a[4][4], b[2][4];
            #pragma unroll
            for (int mf = 0; mf < 4; mf++) {
                int row = wm + mf * 16 + (lane & 7) + ((lane >> 3) & 1) * 8;
                int c = k16 * 2 + (lane >> 4);
                LDSM4(a[mf], ab + row * 128 + ((c ^ (row & 7)) * 16));
            }
            #pragma unroll
            for (int nf2 = 0; nf2 < 2; nf2++) {
                int row = wn + nf2 * 16 + (lane & 7) + ((lane >> 4) & 1) * 8;
                int c = k16 * 2 + ((lane >> 3) & 1);
                LDSM4(b[nf2], bb + row * 128 + ((c ^ (row & 7)) * 16));
            }
            #pragma unroll
            for (int mf = 0; mf < 4; mf++)
                #pragma unroll
                for (int nf = 0; nf < 4; nf++)
                    MMA16816(acc[mf][nf], a[mf],
                             b[nf >> 1][(nf & 1) * 2], b[nf >> 1][(nf & 1) * 2 + 1]);
        }
        __syncthreads();
    }

    #pragma unroll
    for (int mf = 0; mf < 4; mf++) {
        #pragma unroll
        for (int nf = 0; nf < 4; nf++) {
            int r  = m0 + wm + mf * 16 + (lane >> 2);
            int cg = n0 + wn + nf * 8 + (lane & 3) * 2;
            float b0 = bias[cg], b1 = bias[cg + 1];
            float2 v0 = make_float2(acc[mf][nf][0] + b0, acc[mf][nf][1] + b1);
            float2 v1 = make_float2(acc[mf][nf][2] + b0, acc[mf][nf][3] + b1);
            *(float2*)(out + (size_t)r * Vv + cg) = v0;
            *(float2*)(out + (size_t)(r + 8) * Vv + cg) = v1;
        }
    }
}

// ---------------- fused log_softmax (proven R10) -----------------------------
__global__ void lsm_kernel(float* __restrict__ out) {
    extern __shared__ float rowbuf[];
    __shared__ float warpred[8];
    __shared__ float s_bcast;
    const int tid = threadIdx.x;
    const int lane = tid & 31, wid = tid >> 5;
    float* p = out + (size_t)blockIdx.x * Vv;

    float mx = -1e30f;
    for (int i = tid; i < Vv / 4; i += 256) {
        float4 v = *(const float4*)(p + i * 4);
        *(float4*)(rowbuf + i * 4) = v;
        mx = fmaxf(mx, fmaxf(fmaxf(v.x, v.y), fmaxf(v.z, v.w)));
    }
    #pragma unroll
    for (int s = 16; s > 0; s >>= 1)
        mx = fmaxf(mx, __shfl_xor_sync(0xffffffffu, mx, s));
    if (lane == 0) warpred[wid] = mx;
    __syncthreads();
    mx = warpred[lane & 7];
    #pragma unroll
    for (int s = 4; s > 0; s >>= 1)
        mx = fmaxf(mx, __shfl_xor_sync(0xffffffffu, mx, s));
    mx = __shfl_sync(0xffffffffu, mx, 0);

    float sum = 0.f;
    for (int i = tid; i < Vv; i += 256) sum += fast_exp(rowbuf[i] - mx);
    #pragma unroll
    for (int s = 16; s > 0; s >>= 1)
        sum += __shfl_xor_sync(0xffffffffu, sum, s);
    __syncthreads();
    if (lane == 0) warpred[wid] = sum;
    __syncthreads();
    if (tid == 0) {
        float tot = 0.f;
        #pragma unroll
        for (int w = 0; w < 8; w++) tot += warpred[w];
        s_bcast = mx + logf(tot);
    }
    __syncthreads();
    float lse = s_bcast;

    for (int i = tid; i < Vv / 4; i += 256) {
        float4 v = *(const float4*)(rowbuf + i * 4);
        v.x -= lse; v.y -= lse; v.z -= lse; v.w -= lse;
        *(float4*)(p + i * 4) = v;
    }
}

// ---------------- host driver ------------------------------------------------
extern "C" void kernel_launch(void* const* d_in, const int* in_sizes, int n_in,
                              void* d_out, int out_size) {
    const float* enc_h  = (const float*)d_in[1];
    const int*   target = (const int*)  d_in[2];
    const float* emb    = (const float*)d_in[3];
    const float* w_ih   = (const float*)d_in[4];
    const float* w_hh   = (const float*)d_in[5];
    const float* b_ih   = (const float*)d_in[6];
    const float* b_hh   = (const float*)d_in[7];
    const float* w_out  = (const float*)d_in[8];
    const float* b_out  = (const float*)d_in[9];
    float* out = (float*)d_out;

    float *p_gi, *p_h0, *p_hbuf;
    __nv_bfloat16 *p_hsb, *p_wob;
    cudaGetSymbolAddress((void**)&p_gi,   g_gi);
    cudaGetSymbolAddress((void**)&p_h0,   g_h0);
    cudaGetSymbolAddress((void**)&p_hsb,  g_hsb);
    cudaGetSymbolAddress((void**)&p_wob,  g_wob);
    cudaGetSymbolAddress((void**)&p_hbuf, g_hbuf);

    float* hfinal = out + (size_t)MROWS * Vv;

    cudaFuncSetAttribute(logits_mma_kernel,
                         cudaFuncAttributeMaxDynamicSharedMemorySize, LSMEM);
    cudaFuncSetAttribute(gi_mma_kernel<0>,
                         cudaFuncAttributeMaxDynamicSharedMemorySize, GSMEM);
    cudaFuncSetAttribute(gi_mma_kernel<1>,
                         cudaFuncAttributeMaxDynamicSharedMemorySize, GSMEM);
    cudaFuncSetAttribute(gru_layer_kernel,
                         cudaFuncAttributeMaxDynamicSharedMemorySize, GRUSM);
    cudaFuncSetAttribute(lsm_kernel,
                         cudaFuncAttributeMaxDynamicSharedMemorySize, LSMSZ);

    // prep
    ids_kernel<<<(MROWS + 255) / 256, 256, 0, 0>>>(target);
    wconv_kernel<<<4096, 256, 0, 0>>>(w_out);

    // ---- layer 0 -----------------------------------------------------------
    gi_mma_kernel<1><<<dim3(H3 / 128, MROWS / 128), 256, GSMEM, 0>>>(
        nullptr, w_ih, b_ih, p_gi, emb);
    copy_kernel<<<(Bb * Hh + 255) / 256, 256, 0, 0>>>(enc_h, p_hbuf, Bb * Hh);
    zero_bar_kernel<<<1, 1, 0, 0>>>();
    gru_layer_kernel<<<NBLK, 256, GRUSM, 0>>>(
        p_gi, w_hh, b_hh, p_h0, nullptr, hfinal, Bb * Hh, Hh);

    // ---- layer 1 -----------------------------------------------------------
    gi_mma_kernel<0><<<dim3(H3 / 128, MROWS / 128), 256, GSMEM, 0>>>(
        p_h0, w_ih + (size_t)H3 * Hh, b_ih + H3, p_gi, nullptr);
    copy_kernel<<<(Bb * Hh + 255) / 256, 256, 0, 0>>>(
        enc_h + Bb * Hh, p_hbuf, Bb * Hh);
    zero_bar_kernel<<<1, 1, 0, 0>>>();
    gru_layer_kernel<<<NBLK, 256, GRUSM, 0>>>(
        p_gi, w_hh + (size_t)H3 * Hh, b_hh + H3, nullptr, p_hsb,
        hfinal + Bb * Hh, Hh, Tt * Hh);

    // ---- logits (bf16 HMMA) ------------------------------------------------
    logits_mma_kernel<<<dim3(Vv / NT, MROWS / MT), 256, LSMEM, 0>>>(
        p_hsb, p_wob, b_out, out);

    // ---- fused log_softmax -------------------------------------------------
    lsm_kernel<<<MROWS, 256, LSMSZ, 0>>>(out);
}

// round 12
// speedup vs baseline: 6.9913x; 1.1136x over previous
#include <cuda_runtime.h>
#include <cuda_bf16.h>
#include <math.h>
#include <stdint.h>

// Problem constants
#define Bb 32
#define Tt 128
#define Hh 1024
#define Ll 2
#define Vv 32000
#define H3 3072          // 3*H
#define MROWS (Tt*Bb)    // 4096
#define BOS 1
#define NBLK 128         // persistent recurrence blocks (all resident)

// Logits HMMA tiling (bf16)
#define MT 128
#define NT 128
#define KC 64
#define NKC (Hh / KC)
#define ATILEB (MT * 128)
#define BTILEB (NT * 128)
#define LSMEM (2 * (ATILEB + BTILEB))   // 64 KB

// gi GEMM tiling (tf32)
#define GKC 32
#define GNKC (Hh / GKC)
#define GTILEB (128 * 128)
#define GSMEM (4 * GTILEB)              // 64 KB

// GRU smem: A(h) 32x1024 fp32 = 128KB, B(whh slice tf32) 24x1024 = 96KB
#define GRUSM (32 * 4096 + 24 * 4096)   // 229376 B

// fused log_softmax smem (one row)
#define LSMSZ (Vv * 4)

// ---------------- scratch (static device globals) ---------------------------
__device__ float g_gi[MROWS * H3];
__device__ float g_h0[MROWS * Hh];
__device__ __nv_bfloat16 g_hsb[MROWS * Hh];
__device__ __nv_bfloat16 g_wob[(size_t)Vv * Hh];
__device__ float g_hbuf[2][Bb * Hh];
__device__ int   g_ids[MROWS];
__device__ unsigned g_bar;

// ---------------- PTX helpers (all arch-portable: sm_80+) --------------------
__device__ __forceinline__ uint32_t smem_u32(const void* p) {
    uint32_t a;
    asm("{ .reg .u64 t; cvta.to.shared.u64 t, %1; cvt.u32.u64 %0, t; }"
        : "=r"(a) : "l"(p));
    return a;
}
__device__ __forceinline__ void cp_async16(uint32_t s, const void* g) {
    asm volatile("cp.async.cg.shared.global [%0], [%1], 16;"
                 :: "r"(s), "l"(g) : "memory");
}
#define CP_COMMIT() asm volatile("cp.async.commit_group;" ::: "memory")
#define CP_WAIT1()  asm volatile("cp.async.wait_group 1;" ::: "memory")
#define CP_WAIT0()  asm volatile("cp.async.wait_group 0;" ::: "memory")
#define LDSM4(r, addr) \
    asm volatile("ldmatrix.sync.aligned.m8n8.x4.shared.b16 {%0,%1,%2,%3}, [%4];" \
        : "=r"((r)[0]), "=r"((r)[1]), "=r"((r)[2]), "=r"((r)[3]) : "r"(addr))
#define MMA16816(c, a, b0, b1) \
    asm volatile("mma.sync.aligned.m16n8k16.row.col.f32.bf16.bf16.f32 " \
        "{%0,%1,%2,%3}, {%4,%5,%6,%7}, {%8,%9}, {%0,%1,%2,%3};" \
        : "+f"((c)[0]), "+f"((c)[1]), "+f"((c)[2]), "+f"((c)[3]) \
        : "r"((a)[0]), "r"((a)[1]), "r"((a)[2]), "r"((a)[3]), "r"(b0), "r"(b1))
#define MMA1688TF(c, a, b0, b1) \
    asm volatile("mma.sync.aligned.m16n8k8.row.col.f32.tf32.tf32.f32 " \
        "{%0,%1,%2,%3}, {%4,%5,%6,%7}, {%8,%9}, {%0,%1,%2,%3};" \
        : "+f"((c)[0]), "+f"((c)[1]), "+f"((c)[2]), "+f"((c)[3]) \
        : "r"((a)[0]), "r"((a)[1]), "r"((a)[2]), "r"((a)[3]), "r"(b0), "r"(b1))

__device__ __forceinline__ uint32_t lds_tf32(uint32_t addr) {
    float v; uint32_t o;
    asm("ld.shared.f32 %0, [%1];" : "=f"(v) : "r"(addr));
    asm("cvt.rna.tf32.f32 %0, %1;" : "=r"(o) : "f"(v));
    return o;
}
__device__ __forceinline__ uint32_t lds_u32(uint32_t addr) {
    uint32_t v;
    asm("ld.shared.b32 %0, [%1];" : "=r"(v) : "r"(addr));
    return v;
}
__device__ __forceinline__ uint32_t f2tf(float v) {
    uint32_t o;
    asm("cvt.rna.tf32.f32 %0, %1;" : "=r"(o) : "f"(v));
    return o;
}
// swizzle for 32-float (128B) rows
__device__ __forceinline__ uint32_t swz32(int r, int c) {
    return r * 128 + (((c >> 2) ^ (r & 7)) << 4) + ((c & 3) << 2);
}
// swizzle for 1024-float (4KB) rows
__device__ __forceinline__ uint32_t swzH(int r, int c) {
    return r * 4096 + ((((c >> 2) ^ (r & 7)) & 0xFFFF) << 4) + ((c & 3) << 2);
}

// FFMA-only e^x
__device__ __forceinline__ float fast_exp(float x) {
    float t = fmaxf(x * 1.4426950408889634f, -126.0f);
    float n = floorf(t);
    float f = t - n;
    float p = 0.0001540353f;
    p = p * f + 0.0013333558f;
    p = p * f + 0.0096181291f;
    p = p * f + 0.0555041087f;
    p = p * f + 0.2402265070f;
    p = p * f + 0.6931471806f;
    p = p * f + 1.0f;
    return __int_as_float(((int)n + 127) << 23) * p;
}

// ---------------- tiny helpers ----------------------------------------------
__global__ void copy_kernel(const float* __restrict__ src, float* __restrict__ dst, int n) {
    int i = blockIdx.x * blockDim.x + threadIdx.x;
    if (i < n) dst[i] = src[i];
}
__global__ void zero_bar_kernel() { g_bar = 0u; }
__global__ void wconv_kernel(const float* __restrict__ w) {
    size_t n = (size_t)Vv * Hh;
    size_t stride = (size_t)gridDim.x * blockDim.x;
    for (size_t i = blockIdx.x * (size_t)blockDim.x + threadIdx.x; i < n; i += stride)
        g_wob[i] = __float2bfloat16(w[i]);
}
__global__ void ids_kernel(const int* __restrict__ target) {
    int i = blockIdx.x * blockDim.x + threadIdx.x;
    if (i >= MROWS) return;
    int t = i / Bb, b = i % Bb;
    g_ids[i] = (t == 0) ? BOS : target[b * Tt + (t - 1)];
}

// ---------------- persistent GRU layer: tf32 HMMA recurrence -----------------
// 128 blocks x 256 thr (1/SM, all resident). Block owns 8 h-cols = 24 whh
// rows staged once (tf32). Per step: each WARP cp.asyncs only its own 128-col
// K-slice of h (own-group wait + syncwarp; no block-wide staging sync), tf32
// m16n8k8 MMA, 8-way cross-warp reduce via smem (aliased into dead A region),
// gate math on values prefetched at step start, ping-pong h, grid barrier.
__global__ void __launch_bounds__(256) gru_layer_kernel(
    const float* __restrict__ gi,     // [T][B][3H]
    const float* __restrict__ whh,    // [3H][H]
    const float* __restrict__ bhh,    // [3H]
    float* __restrict__ hist,         // fp32 history (or null)
    __nv_bfloat16* __restrict__ histb,// bf16 history (or null)
    float* __restrict__ hfin,         // final h destination [B][H]
    int tS, int bS)
{
    extern __shared__ float smf[];
    float* part = smf;                 // [8][792] aliased into A region
    float* ghS  = smf + 6400;          // [24*33]  aliased into A region
    const uint32_t aBase = smem_u32(smf);
    const uint32_t bBase = aBase + 32 * 4096;

    const int tid  = threadIdx.x;
    const int lane = tid & 31;
    const int w    = tid >> 5;
    const int j0   = blockIdx.x * 8;

    const int gb = tid >> 3;          // gate-math batch 0..31
    const int gj = tid & 7;           // gate-math col 0..7
    const int j  = j0 + gj;
    const float bhr = bhh[j];
    const float bhz = bhh[Hh + j];
    const float bhn = bhh[2 * Hh + j];

    // ---- stage whh slice (24 rows) into smem, pre-converted to tf32 --------
    for (int idx = tid; idx < 24 * 256; idx += 256) {
        int n = idx >> 8, c = idx & 255;
        int grow = (n >> 3) * Hh + j0 + (n & 7);
        float4 v = *(const float4*)(whh + (size_t)grow * Hh + c * 4);
        uint4 o = make_uint4(f2tf(v.x), f2tf(v.y), f2tf(v.z), f2tf(v.w));
        *(uint4*)((char*)smf + (bBase - aBase) + n * 4096 + (((c ^ (n & 7)) & 0xFFFF) << 4)) = o;
    }
    __syncthreads();

    for (int t = 0; t < Tt; t++) {
        const float* __restrict__ hcur = g_hbuf[t & 1];
        float* __restrict__ hnxt = g_hbuf[(t + 1) & 1];

        // ---- prefetch gi[t] + hprev (consumed post-MMA; latency hidden) ----
        const float* git = gi + ((size_t)t * Bb + gb) * H3;
        float gir = git[j];
        float giz = git[Hh + j];
        float gin = git[2 * Hh + j];
        float hp  = hcur[(size_t)gb * Hh + j];

        // ---- per-warp stage of own K-slice (cols w*128..w*128+127) ----------
        {
            const int c = w * 32 + lane;      // col-quad 0..255
            #pragma unroll 8
            for (int row = 0; row < 32; row++) {
                cp_async16(aBase + row * 4096 + (((c ^ (row & 7)) & 0xFF) << 4),
                           hcur + (size_t)row * Hh + c * 4);
            }
        }
        CP_COMMIT();
        CP_WAIT0();
        __syncwarp();

        // ---- tf32 MMA: warp w covers k in [w*128, w*128+128) ---------------
        float acc[2][3][4];
        #pragma unroll
        for (int m = 0; m < 2; m++)
            #pragma unroll
            for (int nf = 0; nf < 3; nf++)
                #pragma unroll
                for (int q = 0; q < 4; q++) acc[m][nf][q] = 0.f;

        const int k0w = w * 128;
        #pragma unroll
        for (int k8 = 0; k8 < 16; k8++) {
            const int k0 = k0w + k8 * 8;
            const int cA = k0 + (lane & 3);
            uint32_t a[2][4], b[3][2];
            #pragma unroll
            for (int m = 0; m < 2; m++) {
                int r = m * 16 + (lane >> 2);
                a[m][0] = lds_tf32(aBase + swzH(r, cA));
                a[m][1] = lds_tf32(aBase + swzH(r + 8, cA));
                a[m][2] = lds_tf32(aBase + swzH(r, cA + 4));
                a[m][3] = lds_tf32(aBase + swzH(r + 8, cA + 4));
            }
            #pragma unroll
            for (int nf = 0; nf < 3; nf++) {
                int rn = nf * 8 + (lane >> 2);
                b[nf][0] = lds_u32(bBase + swzH(rn, cA));
                b[nf][1] = lds_u32(bBase + swzH(rn, cA + 4));
            }
            #pragma unroll
            for (int m = 0; m < 2; m++)
                #pragma unroll
                for (int nf = 0; nf < 3; nf++)
                    MMA1688TF(acc[m][nf], a[m], b[nf][0], b[nf][1]);
        }
        __syncthreads();   // all MMA reads of A done before aliased writes

        // ---- write partials: part[w][n*33 + m] ------------------------------
        #pragma unroll
        for (int m = 0; m < 2; m++) {
            #pragma unroll
            for (int nf = 0; nf < 3; nf++) {
                int rowm = m * 16 + (lane >> 2);
                int col = nf * 8 + 2 * (lane & 3);
                float* pw = part + w * 792;
                pw[col * 33 + rowm]           = acc[m][nf][0];
                pw[(col + 1) * 33 + rowm]     = acc[m][nf][1];
                pw[col * 33 + rowm + 8]       = acc[m][nf][2];
                pw[(col + 1) * 33 + rowm + 8] = acc[m][nf][3];
            }
        }
        __syncthreads();

        // ---- 8-way reduce -> ghS[n*33 + m] ----------------------------------
        #pragma unroll
        for (int rep = 0; rep < 3; rep++) {
            int p = rep * 256 + tid;          // p = n*32 + m
            int n = p >> 5, m = p & 31;
            float s = 0.f;
            #pragma unroll
            for (int ww = 0; ww < 8; ww++) s += part[ww * 792 + n * 33 + m];
            ghS[n * 33 + m] = s;
        }
        __syncthreads();

        // ---- gate math for owned (gb, j) ------------------------------------
        {
            float ghr = ghS[gj * 33 + gb] + bhr;
            float ghz = ghS[(8 + gj) * 33 + gb] + bhz;
            float ghn = ghS[(16 + gj) * 33 + gb] + bhn;
            float r_ = 1.f / (1.f + expf(-(gir + ghr)));
            float z_ = 1.f / (1.f + expf(-(giz + ghz)));
            float n_ = tanhf(gin + r_ * ghn);
            float hn = (1.f - z_) * n_ + z_ * hp;
            size_t oidx = (size_t)t * tS + (size_t)gb * bS + j;
            if (histb) histb[oidx] = __float2bfloat16(hn);
            else       hist[oidx] = hn;
            hnxt[(size_t)gb * Hh + j] = hn;
            if (t == Tt - 1) hfin[(size_t)gb * Hh + j] = hn;
        }

        // ---- grid barrier ----------------------------------------------------
        __threadfence();
        __syncthreads();
        if (tid == 0) {
            atomicAdd(&g_bar, 1u);
            unsigned tgt = (unsigned)(NBLK * (t + 1));
            volatile unsigned* vb = &g_bar;
            while (*vb < tgt) { __nanosleep(32); }
        }
        __syncthreads();
        __threadfence();
    }
}

// ---------------- tf32 gi GEMM (proven R10) ----------------------------------
#define GPREF(ch, p) do {                                                       \
    int _k0 = (ch) * GKC;                                                       \
    uint32_t _ab = sb + (p) * GTILEB;                                           \
    uint32_t _bb = sb + 2 * GTILEB + (p) * GTILEB;                              \
    _Pragma("unroll")                                                           \
    for (int _it = 0; _it < 4; _it++) {                                         \
        int _idx = _it * 256 + tid, _row = _idx >> 3, _c = _idx & 7;            \
        const float* _as = GATHER                                               \
            ? emb + (size_t)g_ids[m0 + _row] * Hh + _k0 + _c * 4                \
            : A + (size_t)(m0 + _row) * Hh + _k0 + _c * 4;                      \
        cp_async16(_ab + _row * 128 + ((_c ^ (_row & 7)) * 16), _as);           \
        cp_async16(_bb + _row * 128 + ((_c ^ (_row & 7)) * 16),                 \
                   W + (size_t)(n0 + _row) * Hh + _k0 + _c * 4);                \
    }                                                                           \
    CP_COMMIT();                                                                \
} while (0)

template<int GATHER>
__global__ void __launch_bounds__(256) gi_mma_kernel(
    const float* __restrict__ A, const float* __restrict__ W,
    const float* __restrict__ bias, float* __restrict__ C,
    const float* __restrict__ emb)
{
    extern __shared__ char smem[];
    const int tid  = threadIdx.x;
    const int lane = tid & 31;
    const int warp = tid >> 5;
    const int m0 = blockIdx.y * 128;
    const int n0 = blockIdx.x * 128;
    const int wm = (warp & 1) * 64;
    const int wn = (warp >> 1) * 32;
    uint32_t sb = smem_u32(smem);

    float acc[4][4][4];
    #pragma unroll
    for (int i = 0; i < 4; i++)
        #pragma unroll
        for (int jj = 0; jj < 4; jj++)
            #pragma unroll
            for (int k = 0; k < 4; k++) acc[i][jj][k] = 0.f;

    GPREF(0, 0);
    for (int ch = 0; ch < GNKC; ch++) {
        const int p = ch & 1;
        if (ch + 1 < GNKC) { GPREF(ch + 1, (ch + 1) & 1); CP_WAIT1(); }
        else               { CP_WAIT0(); }
        __syncthreads();

        const uint32_t ab = sb + p * GTILEB;
        const uint32_t bb = sb + 2 * GTILEB + p * GTILEB;
        #pragma unroll
        for (int k8 = 0; k8 < 4; k8++) {
            uint32_t a[4][4], b[4][2];
            #pragma unroll
            for (int mf = 0; mf < 4; mf++) {
                int r = wm + mf * 16 + (lane >> 2);
                int c = k8 * 8 + (lane & 3);
                a[mf][0] = lds_tf32(ab + swz32(r, c));
                a[mf][1] = lds_tf32(ab + swz32(r + 8, c));
                a[mf][2] = lds_tf32(ab + swz32(r, c + 4));
                a[mf][3] = lds_tf32(ab + swz32(r + 8, c + 4));
            }
            #pragma unroll
            for (int nf = 0; nf < 4; nf++) {
                int rn = wn + nf * 8 + (lane >> 2);
                int ck = k8 * 8 + (lane & 3);
                b[nf][0] = lds_tf32(bb + swz32(rn, ck));
                b[nf][1] = lds_tf32(bb + swz32(rn, ck + 4));
            }
            #pragma unroll
            for (int mf = 0; mf < 4; mf++)
                #pragma unroll
                for (int nf = 0; nf < 4; nf++)
                    MMA1688TF(acc[mf][nf], a[mf], b[nf][0], b[nf][1]);
        }
        __syncthreads();
    }

    #pragma unroll
    for (int mf = 0; mf < 4; mf++) {
        #pragma unroll
        for (int nf = 0; nf < 4; nf++) {
            int r  = m0 + wm + mf * 16 + (lane >> 2);
            int cg = n0 + wn + nf * 8 + (lane & 3) * 2;
            float b0 = bias[cg], b1 = bias[cg + 1];
            float2 v0 = make_float2(acc[mf][nf][0] + b0, acc[mf][nf][1] + b1);
            float2 v1 = make_float2(acc[mf][nf][2] + b0, acc[mf][nf][3] + b1);
            *(float2*)(C + (size_t)r * H3 + cg) = v0;
            *(float2*)(C + (size_t)(r + 8) * H3 + cg) = v1;
        }
    }
}

// ---------------- bf16 HMMA logits GEMM (proven R9) --------------------------
#define PREF(ch, p) do {                                                        \
    int _k0 = (ch) * KC;                                                        \
    uint32_t _ab = sb + (p) * ATILEB;                                           \
    uint32_t _bb = sb + 2 * ATILEB + (p) * BTILEB;                              \
    _Pragma("unroll")                                                           \
    for (int _it = 0; _it < 4; _it++) {                                         \
        int _idx = _it * 256 + tid, _row = _idx >> 3, _c = _idx & 7;            \
        cp_async16(_ab + _row * 128 + ((_c ^ (_row & 7)) * 16),                 \
                   hsb + (size_t)(m0 + _row) * Hh + _k0 + _c * 8);              \
        cp_async16(_bb + _row * 128 + ((_c ^ (_row & 7)) * 16),                 \
                   wob + (size_t)(n0 + _row) * Hh + _k0 + _c * 8);              \
    }                                                                           \
    CP_COMMIT();                                                                \
} while (0)

__global__ void __launch_bounds__(256) logits_mma_kernel(
    const __nv_bfloat16* __restrict__ hsb,
    const __nv_bfloat16* __restrict__ wob,
    const float* __restrict__ bias,
    float* __restrict__ out)
{
    extern __shared__ char smem[];
    const int tid  = threadIdx.x;
    const int lane = tid & 31;
    const int warp = tid >> 5;
    const int m0 = blockIdx.y * MT;
    const int n0 = blockIdx.x * NT;
    const int wm = (warp & 1) * 64;
    const int wn = (warp >> 1) * 32;
    uint32_t sb = smem_u32(smem);

    float acc[4][4][4];
    #pragma unroll
    for (int i = 0; i < 4; i++)
        #pragma unroll
        for (int jj = 0; jj < 4; jj++)
            #pragma unroll
            for (int k = 0; k < 4; k++) acc[i][jj][k] = 0.f;

    PREF(0, 0);
    for (int ch = 0; ch < NKC; ch++) {
        const int p = ch & 1;
        if (ch + 1 < NKC) { PREF(ch + 1, (ch + 1) & 1); CP_WAIT1(); }
        else              { CP_WAIT0(); }
        __syncthreads();

        const uint32_t ab = sb + p * ATILEB;
        const uint32_t bb = sb + 2 * ATILEB + p * BTILEB;
        #pragma unroll
        for (int k16 = 0; k16 < 4; k16++) {
            uint32_t a[4][4], b[2][4];
            #pragma unroll
            for (int mf = 0; mf < 4; mf++) {
                int row = wm + mf * 16 + (lane & 7) + ((lane >> 3) & 1) * 8;
                int c = k16 * 2 + (lane >> 4);
                LDSM4(a[mf], ab + row * 128 + ((c ^ (row & 7)) * 16));
            }
            #pragma unroll
            for (int nf2 = 0; nf2 < 2; nf2++) {
                int row = wn + nf2 * 16 + (lane & 7) + ((lane >> 4) & 1) * 8;
                int c = k16 * 2 + ((lane >> 3) & 1);
                LDSM4(b[nf2], bb + row * 128 + ((c ^ (row & 7)) * 16));
            }
            #pragma unroll
            for (int mf = 0; mf < 4; mf++)
                #pragma unroll
                for (int nf = 0; nf < 4; nf++)
                    MMA16816(acc[mf][nf], a[mf],
                             b[nf >> 1][(nf & 1) * 2], b[nf >> 1][(nf & 1) * 2 + 1]);
        }
        __syncthreads();
    }

    #pragma unroll
    for (int mf = 0; mf < 4; mf++) {
        #pragma unroll
        for (int nf = 0; nf < 4; nf++) {
            int r  = m0 + wm + mf * 16 + (lane >> 2);
            int cg = n0 + wn + nf * 8 + (lane & 3) * 2;
            float b0 = bias[cg], b1 = bias[cg + 1];
            float2 v0 = make_float2(acc[mf][nf][0] + b0, acc[mf][nf][1] + b1);
            float2 v1 = make_float2(acc[mf][nf][2] + b0, acc[mf][nf][3] + b1);
            *(float2*)(out + (size_t)r * Vv + cg) = v0;
            *(float2*)(out + (size_t)(r + 8) * Vv + cg) = v1;
        }
    }
}

// ---------------- fused log_softmax (512 threads) ----------------------------
__global__ void lsm_kernel(float* __restrict__ out) {
    extern __shared__ float rowbuf[];
    __shared__ float warpred[16];
    __shared__ float s_bcast;
    const int tid = threadIdx.x;
    const int lane = tid & 31, wid = tid >> 5;
    float* p = out + (size_t)blockIdx.x * Vv;

    float mx = -1e30f;
    for (int i = tid; i < Vv / 4; i += 512) {
        float4 v = *(const float4*)(p + i * 4);
        *(float4*)(rowbuf + i * 4) = v;
        mx = fmaxf(mx, fmaxf(fmaxf(v.x, v.y), fmaxf(v.z, v.w)));
    }
    #pragma unroll
    for (int s = 16; s > 0; s >>= 1)
        mx = fmaxf(mx, __shfl_xor_sync(0xffffffffu, mx, s));
    if (lane == 0) warpred[wid] = mx;
    __syncthreads();
    mx = warpred[lane & 15];
    #pragma unroll
    for (int s = 8; s > 0; s >>= 1)
        mx = fmaxf(mx, __shfl_xor_sync(0xffffffffu, mx, s));
    mx = __shfl_sync(0xffffffffu, mx, 0);

    float sum = 0.f;
    for (int i = tid; i < Vv; i += 512) sum += fast_exp(rowbuf[i] - mx);
    #pragma unroll
    for (int s = 16; s > 0; s >>= 1)
        sum += __shfl_xor_sync(0xffffffffu, sum, s);
    __syncthreads();
    if (lane == 0) warpred[wid] = sum;
    __syncthreads();
    if (tid == 0) {
        float tot = 0.f;
        #pragma unroll
        for (int w = 0; w < 16; w++) tot += warpred[w];
        s_bcast = mx + logf(tot);
    }
    __syncthreads();
    float lse = s_bcast;

    for (int i = tid; i < Vv / 4; i += 512) {
        float4 v = *(const float4*)(rowbuf + i * 4);
        v.x -= lse; v.y -= lse; v.z -= lse; v.w -= lse;
        *(float4*)(p + i * 4) = v;
    }
}

// ---------------- host driver ------------------------------------------------
extern "C" void kernel_launch(void* const* d_in, const int* in_sizes, int n_in,
                              void* d_out, int out_size) {
    const float* enc_h  = (const float*)d_in[1];
    const int*   target = (const int*)  d_in[2];
    const float* emb    = (const float*)d_in[3];
    const float* w_ih   = (const float*)d_in[4];
    const float* w_hh   = (const float*)d_in[5];
    const float* b_ih   = (const float*)d_in[6];
    const float* b_hh   = (const float*)d_in[7];
    const float* w_out  = (const float*)d_in[8];
    const float* b_out  = (const float*)d_in[9];
    float* out = (float*)d_out;

    float *p_gi, *p_h0, *p_hbuf;
    __nv_bfloat16 *p_hsb, *p_wob;
    cudaGetSymbolAddress((void**)&p_gi,   g_gi);
    cudaGetSymbolAddress((void**)&p_h0,   g_h0);
    cudaGetSymbolAddress((void**)&p_hsb,  g_hsb);
    cudaGetSymbolAddress((void**)&p_wob,  g_wob);
    cudaGetSymbolAddress((void**)&p_hbuf, g_hbuf);

    float* hfinal = out + (size_t)MROWS * Vv;

    cudaFuncSetAttribute(logits_mma_kernel,
                         cudaFuncAttributeMaxDynamicSharedMemorySize, LSMEM);
    cudaFuncSetAttribute(gi_mma_kernel<0>,
                         cudaFuncAttributeMaxDynamicSharedMemorySize, GSMEM);
    cudaFuncSetAttribute(gi_mma_kernel<1>,
                         cudaFuncAttributeMaxDynamicSharedMemorySize, GSMEM);
    cudaFuncSetAttribute(gru_layer_kernel,
                         cudaFuncAttributeMaxDynamicSharedMemorySize, GRUSM);
    cudaFuncSetAttribute(lsm_kernel,
                         cudaFuncAttributeMaxDynamicSharedMemorySize, LSMSZ);

    // ---- layer 0 (order arranged so ncu's sample index lands on gi/gru) ----
    copy_kernel<<<(Bb * Hh + 255) / 256, 256, 0, 0>>>(enc_h, p_hbuf, Bb * Hh);
    zero_bar_kernel<<<1, 1, 0, 0>>>();
    ids_kernel<<<(MROWS + 255) / 256, 256, 0, 0>>>(target);
    gi_mma_kernel<1><<<dim3(H3 / 128, MROWS / 128), 256, GSMEM, 0>>>(
        nullptr, w_ih, b_ih, p_gi, emb);
    gru_layer_kernel<<<NBLK, 256, GRUSM, 0>>>(
        p_gi, w_hh, b_hh, p_h0, nullptr, hfinal, Bb * Hh, Hh);

    // ---- w_out conversion (only needed before logits) ----------------------
    wconv_kernel<<<4096, 256, 0, 0>>>(w_out);

    // ---- layer 1 -----------------------------------------------------------
    gi_mma_kernel<0><<<dim3(H3 / 128, MROWS / 128), 256, GSMEM, 0>>>(
        p_h0, w_ih + (size_t)H3 * Hh, b_ih + H3, p_gi, nullptr);
    copy_kernel<<<(Bb * Hh + 255) / 256, 256, 0, 0>>>(
        enc_h + Bb * Hh, p_hbuf, Bb * Hh);
    zero_bar_kernel<<<1, 1, 0, 0>>>();
    gru_layer_kernel<<<NBLK, 256, GRUSM, 0>>>(
        p_gi, w_hh + (size_t)H3 * Hh, b_hh + H3, nullptr, p_hsb,
        hfinal + Bb * Hh, Hh, Tt * Hh);

    // ---- logits (bf16 HMMA) ------------------------------------------------
    logits_mma_kernel<<<dim3(Vv / NT, MROWS / MT), 256, LSMEM, 0>>>(
        p_hsb, p_wob, b_out, out);

    // ---- fused log_softmax -------------------------------------------------
    lsm_kernel<<<MROWS, 512, LSMSZ, 0>>>(out);
}